// round 4
// baseline (speedup 1.0000x reference)
#include <cuda_runtime.h>
#include <math.h>

#define NB   32
#define CC   64
#define LL   1024
#define EPS  1e-6f

// ---------------- scratch (static __device__, no allocation) ----------------
__device__ float g_rn [2][NB*LL];   // 1/||x|| per pixel, per source
__device__ float g_max[2][NB*LL];   // pass0: max2 (rgb rows), pass1: max1 (ir rows)
__device__ float g_sum[2][NB*LL];
__device__ int   g_arg[2][NB*LL];
__device__ float g_part[64];

// ---------------- kernel 1: reciprocal L2 norms over channel dim ------------
__global__ void rnorm_kernel(const float* __restrict__ a, const float* __restrict__ b) {
    int z = blockIdx.z;
    const float* src = z ? b : a;
    int n = blockIdx.y;
    int l = blockIdx.x * 256 + threadIdx.x;
    const float* p = src + n * CC * LL + l;
    float ss = 0.f;
    #pragma unroll
    for (int c = 0; c < CC; ++c) { float x = p[c * LL]; ss += x * x; }
    g_rn[z][n * LL + l] = 1.0f / fmaxf(sqrtf(ss), 1e-12f);
}

// ---------------- kernel 2: row stats of exp(dot/T) for (X rows, Y cols) ----
// BM=128 rows per block, loop all 1024 cols in chunks of 128.
// 256 threads, 8x8 register micro-tile. Inputs read in native [n][c][l] layout.
__global__ __launch_bounds__(256) void stats_kernel(
    const float* __restrict__ X, const float* __restrict__ Y,
    int px, int py, int pout)
{
    __shared__ float As[CC][128];   // 32 KB, full K
    __shared__ float Bs[32][128];   // 16 KB, half-K chunk of B

    int n  = blockIdx.y;
    int i0 = blockIdx.x * 128;
    const float* Xn = X + n * CC * LL;
    const float* Yn = Y + n * CC * LL;
    int tid = threadIdx.x;
    int tx  = tid & 15;
    int ty  = tid >> 4;

    // load A tile: 64 c-rows x 128 i, coalesced float4
    #pragma unroll
    for (int it = 0; it < 8; ++it) {
        int idx = it * 256 + tid;
        int c = idx >> 5, v = idx & 31;
        float4 t = *(const float4*)(Xn + c * LL + i0 + v * 4);
        *(float4*)(&As[c][v * 4]) = t;
    }

    // per-thread row scales (fold 1/TEMP into A side)
    float sA[8];
    #pragma unroll
    for (int r = 0; r < 8; ++r) {
        int il = ty * 4 + (r & 3) + ((r >= 4) ? 64 : 0);
        sA[r] = __ldg(&g_rn[px][n * LL + i0 + il]) * 10.0f;
    }

    float m[8], s[8]; int ia[8];
    #pragma unroll
    for (int r = 0; r < 8; ++r) { m[r] = 0.0f; s[r] = 0.0f; ia[r] = 0; }

    for (int jb = 0; jb < 8; ++jb) {
        int j0 = jb * 128;
        float acc[8][8];
        #pragma unroll
        for (int r = 0; r < 8; ++r)
            #pragma unroll
            for (int q = 0; q < 8; ++q) acc[r][q] = 0.0f;

        #pragma unroll
        for (int ch = 0; ch < 2; ++ch) {
            __syncthreads();   // protect Bs from previous compute (+A tile on first pass)
            #pragma unroll
            for (int it = 0; it < 4; ++it) {
                int idx = it * 256 + tid;
                int c = idx >> 5, v = idx & 31;
                float4 t = *(const float4*)(Yn + (ch * 32 + c) * LL + j0 + v * 4);
                *(float4*)(&Bs[c][v * 4]) = t;
            }
            __syncthreads();

            #pragma unroll 4
            for (int cc = 0; cc < 32; ++cc) {
                float a0[8], b0[8];
                *(float4*)&a0[0] = *(const float4*)&As[ch * 32 + cc][ty * 4];
                *(float4*)&a0[4] = *(const float4*)&As[ch * 32 + cc][64 + ty * 4];
                *(float4*)&b0[0] = *(const float4*)&Bs[cc][tx * 4];
                *(float4*)&b0[4] = *(const float4*)&Bs[cc][64 + tx * 4];
                #pragma unroll
                for (int r = 0; r < 8; ++r)
                    #pragma unroll
                    for (int q = 0; q < 8; ++q)
                        acc[r][q] += a0[r] * b0[q];
            }
        }

        // epilogue: exp + running (max, argmax, sum)
        float sB[8]; int jg[8];
        #pragma unroll
        for (int q = 0; q < 8; ++q) {
            int jl = tx * 4 + (q & 3) + ((q >= 4) ? 64 : 0);
            jg[q] = j0 + jl;
            sB[q] = __ldg(&g_rn[py][n * LL + j0 + jl]);
        }
        #pragma unroll
        for (int r = 0; r < 8; ++r) {
            #pragma unroll
            for (int q = 0; q < 8; ++q) {
                float v = __expf(acc[r][q] * sA[r] * sB[q]);
                if (v > m[r]) { m[r] = v; ia[r] = jg[q]; }
                s[r] += v;
            }
        }
    }

    // reduce (max, arg, sum) across the 16 tx lanes (16-lane segments in warp)
    #pragma unroll
    for (int off = 8; off; off >>= 1) {
        #pragma unroll
        for (int r = 0; r < 8; ++r) {
            float mo = __shfl_down_sync(0xffffffffu, m[r],  off, 16);
            int   io = __shfl_down_sync(0xffffffffu, ia[r], off, 16);
            float so = __shfl_down_sync(0xffffffffu, s[r],  off, 16);
            s[r] += so;
            if (mo > m[r] || (mo == m[r] && io < ia[r])) { m[r] = mo; ia[r] = io; }
        }
    }

    if (tx == 0) {
        #pragma unroll
        for (int r = 0; r < 8; ++r) {
            int il = ty * 4 + (r & 3) + ((r >= 4) ? 64 : 0);
            int gi = n * LL + i0 + il;
            g_max[pout][gi] = m[r];
            g_arg[pout][gi] = ia[r];
            g_sum[pout][gi] = s[r];
        }
    }
}

// ---------------- kernel 3: per-entry -log terms, 64 block partials ---------
// NOTE: reference is max_h/(sum_h + eps) * max_o[arg_h] / (sum_o + eps)
// where sum_o is at the entry's OWN index (elementwise), NOT gathered at arg_h.
__global__ void loss_part_kernel() {
    float acc = 0.f;
    #pragma unroll
    for (int k = 0; k < 4; ++k) {
        int ee = blockIdx.x * 1024 + k * 256 + threadIdx.x;  // 0..65535
        int half = ee >> 15;         // 0: rgb2ir2rgb, 1: ir2rgb2ir
        int idx  = ee & 32767;       // n*L + i
        int o    = half ^ 1;
        float mp = g_max[half][idx], sp = g_sum[half][idx];
        int   a  = g_arg[half][idx];
        int base = idx & ~(LL - 1);
        float mo = g_max[o][base + a];
        float so = g_sum[o][idx];            // own index, not gathered
        acc += __logf(mp / (sp + EPS) * (mo / (so + EPS)));
    }
    __shared__ float red[256];
    red[threadIdx.x] = acc;
    __syncthreads();
    for (int st = 128; st; st >>= 1) {
        if (threadIdx.x < st) red[threadIdx.x] += red[threadIdx.x + st];
        __syncthreads();
    }
    if (threadIdx.x == 0) g_part[blockIdx.x] = red[0];
}

__global__ void loss_final_kernel(float* __restrict__ out) {
    float v = g_part[threadIdx.x] + g_part[threadIdx.x + 32];
    #pragma unroll
    for (int off = 16; off; off >>= 1)
        v += __shfl_down_sync(0xffffffffu, v, off);
    if (threadIdx.x == 0) out[0] = -v * (1.0f / 65536.0f);
}

// ---------------- launch -----------------------------------------------------
extern "C" void kernel_launch(void* const* d_in, const int* in_sizes, int n_in,
                              void* d_out, int out_size) {
    const float* rgb = (const float*)d_in[0];
    const float* ir  = (const float*)d_in[1];

    rnorm_kernel<<<dim3(4, 32, 2), 256>>>(rgb, ir);
    // pass 0: rgb rows vs ir cols  -> max2/arg2/sum2
    stats_kernel<<<dim3(8, 32), 256>>>(rgb, ir, 0, 1, 0);
    // pass 1: ir rows vs rgb cols  -> max1/arg1/sum1
    stats_kernel<<<dim3(8, 32), 256>>>(ir, rgb, 1, 0, 1);
    loss_part_kernel<<<64, 256>>>();
    loss_final_kernel<<<1, 32>>>((float*)d_out);
}

// round 6
// speedup vs baseline: 1.8003x; 1.8003x over previous
#include <cuda_runtime.h>
#include <math.h>

#define NB   32
#define CC   64
#define LL   1024
#define EPS  1e-6f

// ---------------- scratch (static __device__, no allocation) ----------------
__device__ float g_rn [2][NB*LL];            // 1/||x|| per pixel (0=rgb, 1=ir)
__device__ float g_max[2][NB*LL];            // [0]=row stats (max2), [1]=col stats (max1)
__device__ float g_sum[2][NB*LL];
__device__ int   g_arg[2][NB*LL];
__device__ unsigned long long g_ckey[8][NB*LL];  // per-panel col (max,arg) packed
__device__ float              g_csum[8][NB*LL];  // per-panel col sums
__device__ float g_part[64];

// ---------------- kernel 1: reciprocal L2 norms over channel dim ------------
__global__ void rnorm_kernel(const float* __restrict__ a, const float* __restrict__ b) {
    int z = blockIdx.z;
    const float* src = z ? b : a;
    int n = blockIdx.y;
    int l = blockIdx.x * 256 + threadIdx.x;
    const float* p = src + n * CC * LL + l;
    float ss = 0.f;
    #pragma unroll
    for (int c = 0; c < CC; ++c) { float x = p[c * LL]; ss += x * x; }
    g_rn[z][n * LL + l] = 1.0f / fmaxf(sqrtf(ss), 1e-12f);
}

// ---------------- kernel 2: ONE fused pass ----------------------------------
// Computes exp(rgb_i . ir_j * 10 * rn_i * rn_j) once per (i,j).
// Row stats (over j) finalized in-block -> g_*[0].
// Col stats (over i) produced as 8 per-panel partials -> g_ckey/g_csum.
__global__ __launch_bounds__(256, 2) void fused_stats_kernel(
    const float* __restrict__ X, const float* __restrict__ Y)
{
    __shared__ float As[CC][128];                        // 32 KB, full K of X panel
    __shared__ __align__(16) unsigned char BsRaw[32][512]; // 16 KB: Bs, later kbuf+sbuf
    float (*Bs)[128] = (float (*)[128])BsRaw;
    unsigned long long (*kbuf)[128] = (unsigned long long (*)[128])BsRaw;       // 8 KB
    float (*sbuf)[128] = (float (*)[128])((unsigned char*)BsRaw + 8192);        // 4 KB

    int n  = blockIdx.y;
    int i0 = blockIdx.x * 128;
    const float* Xn = X + n * CC * LL;
    const float* Yn = Y + n * CC * LL;
    int tid = threadIdx.x;
    int tx  = tid & 15;
    int ty  = tid >> 4;
    int w   = tid >> 5;

    // load A tile: 64 c-rows x 128 i, coalesced float4
    #pragma unroll
    for (int it = 0; it < 8; ++it) {
        int idx = it * 256 + tid;
        int c = idx >> 5, v = idx & 31;
        float4 t = *(const float4*)(Xn + c * LL + i0 + v * 4);
        *(float4*)(&As[c][v * 4]) = t;
    }

    // per-thread row scales (fold 1/TEMP into row side)
    float sA[8];
    #pragma unroll
    for (int r = 0; r < 8; ++r) {
        int il = ty * 4 + (r & 3) + ((r >= 4) ? 64 : 0);
        sA[r] = __ldg(&g_rn[0][n * LL + i0 + il]) * 10.0f;
    }

    float m[8], s[8]; int ia[8];
    #pragma unroll
    for (int r = 0; r < 8; ++r) { m[r] = 0.0f; s[r] = 0.0f; ia[r] = 0; }

    for (int jb = 0; jb < 8; ++jb) {
        int j0 = jb * 128;
        float acc[8][8];
        #pragma unroll
        for (int r = 0; r < 8; ++r)
            #pragma unroll
            for (int q = 0; q < 8; ++q) acc[r][q] = 0.0f;

        #pragma unroll
        for (int ch = 0; ch < 2; ++ch) {
            __syncthreads();   // Bs (aliased as kbuf/sbuf) free from previous use
            #pragma unroll
            for (int it = 0; it < 4; ++it) {
                int idx = it * 256 + tid;
                int c = idx >> 5, v = idx & 31;
                float4 t = *(const float4*)(Yn + (ch * 32 + c) * LL + j0 + v * 4);
                *(float4*)(&Bs[c][v * 4]) = t;
            }
            __syncthreads();

            #pragma unroll 4
            for (int cc = 0; cc < 32; ++cc) {
                float a0[8], b0[8];
                *(float4*)&a0[0] = *(const float4*)&As[ch * 32 + cc][ty * 4];
                *(float4*)&a0[4] = *(const float4*)&As[ch * 32 + cc][64 + ty * 4];
                *(float4*)&b0[0] = *(const float4*)&Bs[cc][tx * 4];
                *(float4*)&b0[4] = *(const float4*)&Bs[cc][64 + tx * 4];
                #pragma unroll
                for (int r = 0; r < 8; ++r)
                    #pragma unroll
                    for (int q = 0; q < 8; ++q)
                        acc[r][q] += a0[r] * b0[q];
            }
        }

        // ---- epilogue: exp in place + row stats ----
        float sB[8]; int jg[8];
        #pragma unroll
        for (int q = 0; q < 8; ++q) {
            int jl = tx * 4 + (q & 3) + ((q >= 4) ? 64 : 0);
            jg[q] = j0 + jl;
            sB[q] = __ldg(&g_rn[1][n * LL + j0 + jl]);
        }
        #pragma unroll
        for (int r = 0; r < 8; ++r) {
            #pragma unroll
            for (int q = 0; q < 8; ++q) {
                float v = __expf(acc[r][q] * sA[r] * sB[q]);
                acc[r][q] = v;
                if (v > m[r]) { m[r] = v; ia[r] = jg[q]; }
                s[r] += v;
            }
        }

        // ---- col partial stats for these 128 columns ----
        __syncthreads();   // all warps done reading Bs; safe to alias as kbuf/sbuf
        #pragma unroll
        for (int q = 0; q < 8; ++q) {
            float cmv = acc[0][q], csv = acc[0][q];
            int cir = 0;
            #pragma unroll
            for (int r = 1; r < 8; ++r) {
                float v = acc[r][q];
                csv += v;
                if (v > cmv) { cmv = v; cir = r; }   // increasing r = increasing i
            }
            int ig = i0 + ty * 4 + (cir & 3) + ((cir >= 4) ? 64 : 0);
            unsigned long long key =
                ((unsigned long long)__float_as_uint(cmv) << 32) |
                (unsigned)(0xFFFFFFFFu - (unsigned)ig);
            // merge ty pair (lanes l, l+16) within warp
            unsigned long long ko = __shfl_down_sync(0xffffffffu, key, 16);
            float so = __shfl_down_sync(0xffffffffu, csv, 16);
            if ((tid & 16) == 0) {
                csv += so;
                if (ko > key) key = ko;
                int jl = tx * 4 + (q & 3) + ((q >= 4) ? 64 : 0);
                kbuf[w][jl] = key;
                sbuf[w][jl] = csv;
            }
        }
        __syncthreads();
        if (tid < 128) {   // one thread per column: merge 8 warp partials (fixed order)
            unsigned long long key = kbuf[0][tid];
            float sum = sbuf[0][tid];
            #pragma unroll
            for (int ww = 1; ww < 8; ++ww) {
                unsigned long long ko = kbuf[ww][tid];
                if (ko > key) key = ko;
                sum += sbuf[ww][tid];
            }
            g_ckey[blockIdx.x][n * LL + j0 + tid] = key;
            g_csum[blockIdx.x][n * LL + j0 + tid] = sum;
        }
        // loop-top __syncthreads protects kbuf/sbuf before next Bs store
    }

    // ---- finalize row stats: reduce over the 16 tx lanes ----
    #pragma unroll
    for (int off = 8; off; off >>= 1) {
        #pragma unroll
        for (int r = 0; r < 8; ++r) {
            float mo = __shfl_down_sync(0xffffffffu, m[r],  off, 16);
            int   io = __shfl_down_sync(0xffffffffu, ia[r], off, 16);
            float so = __shfl_down_sync(0xffffffffu, s[r],  off, 16);
            s[r] += so;
            if (mo > m[r] || (mo == m[r] && io < ia[r])) { m[r] = mo; ia[r] = io; }
        }
    }
    if (tx == 0) {
        #pragma unroll
        for (int r = 0; r < 8; ++r) {
            int il = ty * 4 + (r & 3) + ((r >= 4) ? 64 : 0);
            int gi = n * LL + i0 + il;
            g_max[0][gi] = m[r];
            g_arg[0][gi] = ia[r];
            g_sum[0][gi] = s[r];
        }
    }
}

// ---------------- kernel 3: merge 8 col partials per column -----------------
__global__ void colmerge_kernel() {
    int idx = blockIdx.x * 256 + threadIdx.x;   // 0 .. NB*LL-1
    unsigned long long key = g_ckey[0][idx];
    float sum = g_csum[0][idx];
    #pragma unroll
    for (int b = 1; b < 8; ++b) {
        unsigned long long ko = g_ckey[b][idx];
        if (ko > key) key = ko;
        sum += g_csum[b][idx];
    }
    g_max[1][idx] = __uint_as_float((unsigned)(key >> 32));
    g_arg[1][idx] = (int)(0xFFFFFFFFu - (unsigned)(key & 0xFFFFFFFFu)) & (LL - 1);
    g_sum[1][idx] = sum;
}

// ---------------- kernel 4: per-entry -log terms, 64 block partials ---------
// reference: max_h/(sum_h + eps) * max_o[arg_h] / (sum_o + eps)
// sum_o is at the entry's OWN index (elementwise), NOT gathered at arg_h.
__global__ void loss_part_kernel() {
    float acc = 0.f;
    #pragma unroll
    for (int k = 0; k < 4; ++k) {
        int ee = blockIdx.x * 1024 + k * 256 + threadIdx.x;  // 0..65535
        int half = ee >> 15;         // 0: rgb2ir2rgb, 1: ir2rgb2ir
        int idx  = ee & 32767;       // n*L + i
        int o    = half ^ 1;
        float mp = g_max[half][idx], sp = g_sum[half][idx];
        int   a  = g_arg[half][idx];
        int base = idx & ~(LL - 1);
        float mo = g_max[o][base + a];
        float so = g_sum[o][idx];            // own index
        acc += __logf(mp / (sp + EPS) * (mo / (so + EPS)));
    }
    __shared__ float red[256];
    red[threadIdx.x] = acc;
    __syncthreads();
    for (int st = 128; st; st >>= 1) {
        if (threadIdx.x < st) red[threadIdx.x] += red[threadIdx.x + st];
        __syncthreads();
    }
    if (threadIdx.x == 0) g_part[blockIdx.x] = red[0];
}

__global__ void loss_final_kernel(float* __restrict__ out) {
    float v = g_part[threadIdx.x] + g_part[threadIdx.x + 32];
    #pragma unroll
    for (int off = 16; off; off >>= 1)
        v += __shfl_down_sync(0xffffffffu, v, off);
    if (threadIdx.x == 0) out[0] = -v * (1.0f / 65536.0f);
}

// ---------------- launch -----------------------------------------------------
extern "C" void kernel_launch(void* const* d_in, const int* in_sizes, int n_in,
                              void* d_out, int out_size) {
    const float* rgb = (const float*)d_in[0];
    const float* ir  = (const float*)d_in[1];

    rnorm_kernel<<<dim3(4, 32, 2), 256>>>(rgb, ir);
    fused_stats_kernel<<<dim3(8, 32), 256>>>(rgb, ir);   // one pass, both stat sets
    colmerge_kernel<<<NB * LL / 256, 256>>>();
    loss_part_kernel<<<64, 256>>>();
    loss_final_kernel<<<1, 32>>>((float*)d_out);
}

// round 10
// speedup vs baseline: 2.4521x; 1.3620x over previous
#include <cuda_runtime.h>
#include <cuda_bf16.h>
#include <math.h>
#include <stdint.h>

#define NB   32
#define CC   64
#define LL   1024
#define EPS  1e-6f

// ---------------- scratch (static __device__, no allocation) ----------------
__device__ __nv_bfloat16 g_abf[2][NB*LL*CC];     // rgb * (sqrt10*rn): [hi,lo][(n*LL+l)*CC+c]
__device__ __nv_bfloat16 g_bbf[2][NB*LL*CC];     // ir  * (sqrt10*rn)
__device__ float g_max[2][NB*LL];                // [0]=row stats, [1]=col stats
__device__ float g_sum[2][NB*LL];
__device__ int   g_arg[2][NB*LL];
__device__ unsigned long long g_ckey[8][NB*LL];  // per-panel col (max,arg) packed
__device__ float              g_csum[8][NB*LL];  // per-panel col sums
__device__ float g_part[64];

#define SW128(o) ((o) ^ (((o) >> 3) & 0x70))

__device__ __forceinline__ uint32_t smem_u32(const void* p) {
    uint32_t a;
    asm("{ .reg .u64 t; cvta.to.shared.u64 t, %1; cvt.u32.u64 %0, t; }" : "=r"(a) : "l"(p));
    return a;
}
__device__ __forceinline__ void ldmx4(uint32_t* r, uint32_t addr) {
    asm volatile("ldmatrix.sync.aligned.m8n8.x4.shared.b16 {%0,%1,%2,%3}, [%4];"
                 : "=r"(r[0]), "=r"(r[1]), "=r"(r[2]), "=r"(r[3]) : "r"(addr));
}
__device__ __forceinline__ void mma16816(float* d, const uint32_t* a, uint32_t b0, uint32_t b1) {
    asm volatile("mma.sync.aligned.m16n8k16.row.col.f32.bf16.bf16.f32 "
                 "{%0,%1,%2,%3}, {%4,%5,%6,%7}, {%8,%9}, {%0,%1,%2,%3};"
                 : "+f"(d[0]), "+f"(d[1]), "+f"(d[2]), "+f"(d[3])
                 : "r"(a[0]), "r"(a[1]), "r"(a[2]), "r"(a[3]), "r"(b0), "r"(b1));
}

// ---------------- kernel 1: normalize+scale+split+transpose ------------------
// out[(n*LL+l)*CC+c] = bf16_split( x[n,c,l] * sqrt(10) / max(||x[n,:,l]||, 1e-12) )
__global__ void prep_kernel(const float* __restrict__ rgb, const float* __restrict__ ir) {
    int z = blockIdx.z;
    const float* src = z ? ir : rgb;
    __nv_bfloat16* dhi = z ? g_bbf[0] : g_abf[0];
    __nv_bfloat16* dlo = z ? g_bbf[1] : g_abf[1];
    int n = blockIdx.y;
    int l = blockIdx.x * 256 + threadIdx.x;
    const float* p = src + n * CC * LL + l;

    float x[CC]; float ss = 0.f;
    #pragma unroll
    for (int c = 0; c < CC; ++c) { x[c] = p[c * LL]; ss += x[c] * x[c]; }
    float sc = 3.16227766016838f / fmaxf(sqrtf(ss), 1e-12f);

    unsigned uh[32], ul[32];
    #pragma unroll
    for (int k = 0; k < 32; ++k) {
        float v0 = x[2*k] * sc, v1 = x[2*k+1] * sc;
        __nv_bfloat16 h0 = __float2bfloat16(v0);
        __nv_bfloat16 h1 = __float2bfloat16(v1);
        __nv_bfloat16 l0 = __float2bfloat16(v0 - __bfloat162float(h0));
        __nv_bfloat16 l1 = __float2bfloat16(v1 - __bfloat162float(h1));
        uh[k] = ((unsigned)__bfloat16_as_ushort(h1) << 16) | __bfloat16_as_ushort(h0);
        ul[k] = ((unsigned)__bfloat16_as_ushort(l1) << 16) | __bfloat16_as_ushort(l0);
    }
    size_t ro = (size_t)(n * LL + l) * 8;
    uint4* ph = (uint4*)dhi + ro;
    uint4* pl = (uint4*)dlo + ro;
    #pragma unroll
    for (int k = 0; k < 8; ++k) {
        ph[k] = make_uint4(uh[4*k], uh[4*k+1], uh[4*k+2], uh[4*k+3]);
        pl[k] = make_uint4(ul[4*k], ul[4*k+1], ul[4*k+2], ul[4*k+3]);
    }
}

// ---------------- kernel 2: HMMA (mma.sync) + fused stats --------------------
// D[128x128] = Ahi.Bhi^T + Ahi.Blo^T + Alo.Bhi^T  (fp32 reg accum); logit = exp(D)
#define OA0   0
#define OA1   16384
#define OB0   32768
#define OB1   49152
#define OCK   65536     // u64[4][128] = 4096
#define OCS   69632     // f32[4][128] = 2048
#define ORK   71680     // u64[2][128] = 2048
#define ORS   73728     // f32[2][128] = 1024
#define SMEM_BYTES 74752

__global__ __launch_bounds__(256, 2) void mma_stats_kernel() {
    extern __shared__ __align__(16) char sm[];
    uint32_t sb = smem_u32(sm);

    int tid  = threadIdx.x;
    int lane = tid & 31;
    int wid  = tid >> 5;
    int wm = wid & 3, wn = wid >> 2;          // 4 m-slices x 2 n-slices
    int m0 = wm * 32;
    int n  = blockIdx.y;
    int i0 = blockIdx.x * 128;

    unsigned long long* colkey = (unsigned long long*)(sm + OCK);
    float*              colsum = (float*)(sm + OCS);
    unsigned long long* rowkey = (unsigned long long*)(sm + ORK);
    float*              rowsum = (float*)(sm + ORS);

    // load A tiles (hi+lo): 128 rows x 128B, SW128-swizzled
    {
        const uint4* s0 = (const uint4*)g_abf[0] + (size_t)(n * LL + i0) * 8;
        const uint4* s1 = (const uint4*)g_abf[1] + (size_t)(n * LL + i0) * 8;
        int sub = tid & 7, rb = tid >> 3;
        #pragma unroll
        for (int p = 0; p < 4; ++p) {
            int row = p * 32 + rb;
            uint32_t off = SW128((uint32_t)(row * 128 + sub * 16));
            *(uint4*)(sm + OA0 + off) = s0[row * 8 + sub];
            *(uint4*)(sm + OA1 + off) = s1[row * 8 + sub];
        }
    }

    int lr = lane >> 2, lc2 = (lane & 3) * 2;

    float rm[4], rs[4]; int rj[4];
    #pragma unroll
    for (int r = 0; r < 4; ++r) { rm[r] = 0.f; rs[r] = 0.f; rj[r] = 0; }

    for (int jb = 0; jb < 8; ++jb) {
        int j0 = jb * 128;
        __syncthreads();   // colkey/colsum free, B consumers of prev jb done
        {
            const uint4* s0 = (const uint4*)g_bbf[0] + (size_t)(n * LL + j0) * 8;
            const uint4* s1 = (const uint4*)g_bbf[1] + (size_t)(n * LL + j0) * 8;
            int sub = tid & 7, rb = tid >> 3;
            #pragma unroll
            for (int p = 0; p < 4; ++p) {
                int row = p * 32 + rb;
                uint32_t off = SW128((uint32_t)(row * 128 + sub * 16));
                *(uint4*)(sm + OB0 + off) = s0[row * 8 + sub];
                *(uint4*)(sm + OB1 + off) = s1[row * 8 + sub];
            }
        }
        __syncthreads();

        float acc[2][8][4];
        #pragma unroll
        for (int mt = 0; mt < 2; ++mt)
            #pragma unroll
            for (int nt = 0; nt < 8; ++nt)
                #pragma unroll
                for (int k = 0; k < 4; ++k) acc[mt][nt][k] = 0.f;

        // 3 precision terms: (Ahi,Bhi), (Ahi,Blo), (Alo,Bhi)
        #pragma unroll
        for (int t = 0; t < 3; ++t) {
            uint32_t bA = sb + ((t == 2) ? OA1 : OA0);
            uint32_t bB = sb + ((t == 1) ? OB1 : OB0);
            #pragma unroll
            for (int kk = 0; kk < 4; ++kk) {
                uint32_t afr[2][4], bfr[4][4];
                #pragma unroll
                for (int mt = 0; mt < 2; ++mt) {
                    uint32_t off = SW128((uint32_t)((m0 + mt * 16 + (lane & 15)) * 128
                                                    + kk * 32 + (lane >> 4) * 16));
                    ldmx4(afr[mt], bA + off);
                }
                #pragma unroll
                for (int np = 0; np < 4; ++np) {
                    uint32_t off = SW128((uint32_t)((wn * 64 + np * 16 + (lane & 15)) * 128
                                                    + kk * 32 + (lane >> 4) * 16));
                    ldmx4(bfr[np], bB + off);
                }
                #pragma unroll
                for (int mt = 0; mt < 2; ++mt)
                    #pragma unroll
                    for (int np = 0; np < 4; ++np) {
                        mma16816(acc[mt][2*np],   afr[mt], bfr[np][0], bfr[np][2]);
                        mma16816(acc[mt][2*np+1], afr[mt], bfr[np][1], bfr[np][3]);
                    }
            }
        }

        // ---- epilogue: exp in place + per-thread row stats ----
        #pragma unroll
        for (int mt = 0; mt < 2; ++mt)
            #pragma unroll
            for (int h = 0; h < 2; ++h) {
                int rid = mt * 2 + h;
                #pragma unroll
                for (int nt = 0; nt < 8; ++nt)
                    #pragma unroll
                    for (int e = 0; e < 2; ++e) {
                        float v = __expf(acc[mt][nt][h * 2 + e]);
                        acc[mt][nt][h * 2 + e] = v;
                        rs[rid] += v;
                        int j = j0 + wn * 64 + nt * 8 + lc2 + e;
                        if (v > rm[rid]) { rm[rid] = v; rj[rid] = j; }
                    }
            }

        // ---- col partials: per (nt,e) column, 4 local rows then 8-lane tree ----
        #pragma unroll
        for (int nt = 0; nt < 8; ++nt)
            #pragma unroll
            for (int e = 0; e < 2; ++e) {
                float v0 = acc[0][nt][e],     v1 = acc[0][nt][2 + e];
                float v2 = acc[1][nt][e],     v3 = acc[1][nt][2 + e];
                float cs = v0; cs += v1; cs += v2; cs += v3;
                float cm = v0; int ri = 0;                 // rows asc: +0,+8,+16,+24
                if (v1 > cm) { cm = v1; ri = 1; }
                if (v2 > cm) { cm = v2; ri = 2; }
                if (v3 > cm) { cm = v3; ri = 3; }
                int grow = i0 + m0 + (ri >> 1) * 16 + (ri & 1) * 8 + lr;
                unsigned long long key =
                    ((unsigned long long)__float_as_uint(cm) << 32) |
                    (unsigned)(0xFFFFFFFFu - (unsigned)grow);
                #pragma unroll
                for (int off = 16; off >= 4; off >>= 1) {
                    unsigned long long ko = __shfl_down_sync(0xffffffffu, key, off);
                    float so = __shfl_down_sync(0xffffffffu, cs, off);
                    cs += so;
                    if (ko > key) key = ko;
                }
                if (lane < 4) {
                    int col = wn * 64 + nt * 8 + lc2 + e;
                    colkey[wm * 128 + col] = key;
                    colsum[wm * 128 + col] = cs;
                }
            }
        __syncthreads();
        if (tid < 128) {   // merge 4 wm partials in fixed order
            unsigned long long key = colkey[tid];
            float sum = colsum[tid];
            #pragma unroll
            for (int w2 = 1; w2 < 4; ++w2) {
                unsigned long long ko = colkey[w2 * 128 + tid];
                if (ko > key) key = ko;
                sum += colsum[w2 * 128 + tid];
            }
            g_ckey[blockIdx.x][n * LL + j0 + tid] = key;
            g_csum[blockIdx.x][n * LL + j0 + tid] = sum;
        }
    }

    // ---- final row stats: 4-lane tree over lc, then 2-way wn merge ----
    #pragma unroll
    for (int off = 2; off >= 1; off >>= 1) {
        #pragma unroll
        for (int r = 0; r < 4; ++r) {
            float mo = __shfl_down_sync(0xffffffffu, rm[r], off);
            int   jo = __shfl_down_sync(0xffffffffu, rj[r], off);
            float so = __shfl_down_sync(0xffffffffu, rs[r], off);
            rs[r] += so;
            if (mo > rm[r] || (mo == rm[r] && jo < rj[r])) { rm[r] = mo; rj[r] = jo; }
        }
    }
    __syncthreads();   // colkey merge done; rowkey region free
    if ((lane & 3) == 0) {
        #pragma unroll
        for (int r = 0; r < 4; ++r) {
            int row = m0 + (r >> 1) * 16 + (r & 1) * 8 + lr;
            rowkey[wn * 128 + row] =
                ((unsigned long long)__float_as_uint(rm[r]) << 32) |
                (unsigned)(0xFFFFFFFFu - (unsigned)rj[r]);
            rowsum[wn * 128 + row] = rs[r];
        }
    }
    __syncthreads();
    if (tid < 128) {
        unsigned long long k0 = rowkey[tid], k1 = rowkey[128 + tid];
        float s = rowsum[tid] + rowsum[128 + tid];
        unsigned long long k = (k1 > k0) ? k1 : k0;
        int gi = n * LL + i0 + tid;
        g_max[0][gi] = __uint_as_float((unsigned)(k >> 32));
        g_arg[0][gi] = (int)(0xFFFFFFFFu - (unsigned)(k & 0xFFFFFFFFu)) & (LL - 1);
        g_sum[0][gi] = s;
    }
}

// ---------------- kernel 3: merge 8 col partials per column ------------------
__global__ void colmerge_kernel() {
    int idx = blockIdx.x * 256 + threadIdx.x;
    unsigned long long key = g_ckey[0][idx];
    float sum = g_csum[0][idx];
    #pragma unroll
    for (int b = 1; b < 8; ++b) {
        unsigned long long ko = g_ckey[b][idx];
        if (ko > key) key = ko;
        sum += g_csum[b][idx];
    }
    g_max[1][idx] = __uint_as_float((unsigned)(key >> 32));
    g_arg[1][idx] = (int)(0xFFFFFFFFu - (unsigned)(key & 0xFFFFFFFFu)) & (LL - 1);
    g_sum[1][idx] = sum;
}

// ---------------- kernel 4: per-entry -log terms ------------------------------
// reference: max_h/(sum_h + eps) * max_o[arg_h] / (sum_o + eps); sum_o at OWN index.
__global__ void loss_part_kernel() {
    float acc = 0.f;
    #pragma unroll
    for (int k = 0; k < 4; ++k) {
        int ee = blockIdx.x * 1024 + k * 256 + threadIdx.x;
        int half = ee >> 15;
        int idx  = ee & 32767;
        int o    = half ^ 1;
        float mp = g_max[half][idx], sp = g_sum[half][idx];
        int   a  = g_arg[half][idx];
        int base = idx & ~(LL - 1);
        float mo = g_max[o][base + a];
        float so = g_sum[o][idx];
        acc += __logf(mp / (sp + EPS) * (mo / (so + EPS)));
    }
    __shared__ float red[256];
    red[threadIdx.x] = acc;
    __syncthreads();
    for (int st = 128; st; st >>= 1) {
        if (threadIdx.x < st) red[threadIdx.x] += red[threadIdx.x + st];
        __syncthreads();
    }
    if (threadIdx.x == 0) g_part[blockIdx.x] = red[0];
}

__global__ void loss_final_kernel(float* __restrict__ out) {
    float v = g_part[threadIdx.x] + g_part[threadIdx.x + 32];
    #pragma unroll
    for (int off = 16; off; off >>= 1)
        v += __shfl_down_sync(0xffffffffu, v, off);
    if (threadIdx.x == 0) out[0] = -v * (1.0f / 65536.0f);
}

// ---------------- launch ------------------------------------------------------
extern "C" void kernel_launch(void* const* d_in, const int* in_sizes, int n_in,
                              void* d_out, int out_size) {
    const float* rgb = (const float*)d_in[0];
    const float* ir  = (const float*)d_in[1];

    cudaFuncSetAttribute(mma_stats_kernel,
                         cudaFuncAttributeMaxDynamicSharedMemorySize, SMEM_BYTES);

    prep_kernel<<<dim3(4, 32, 2), 256>>>(rgb, ir);
    mma_stats_kernel<<<dim3(8, 32), 256, SMEM_BYTES>>>();
    colmerge_kernel<<<NB * LL / 256, 256>>>();
    loss_part_kernel<<<64, 256>>>();
    loss_final_kernel<<<1, 32>>>((float*)d_out);
}

// round 12
// speedup vs baseline: 2.4743x; 1.0091x over previous
#include <cuda_runtime.h>
#include <cuda_bf16.h>
#include <math.h>
#include <stdint.h>

#define NB   32
#define CC   64
#define LL   1024
#define EPS  1e-6f

// ---------------- scratch (static __device__, no allocation) ----------------
__device__ __nv_bfloat16 g_abf[2][NB*LL*CC];     // rgb * (sqrt10*rn): [hi,lo][(n*LL+l)*CC+c]
__device__ __nv_bfloat16 g_bbf[2][NB*LL*CC];     // ir  * (sqrt10*rn)
__device__ float g_max[2][NB*LL];                // [0]=row stats (only [0] used now)
__device__ float g_sum[2][NB*LL];
__device__ int   g_arg[2][NB*LL];
__device__ unsigned long long g_ckey[8][NB*LL];  // per-panel col (max,arg) packed
__device__ float              g_csum[8][NB*LL];  // per-panel col sums
__device__ float g_part[256];

#define SW128(o) ((o) ^ (((o) >> 3) & 0x70))

__device__ __forceinline__ uint32_t smem_u32(const void* p) {
    uint32_t a;
    asm("{ .reg .u64 t; cvta.to.shared.u64 t, %1; cvt.u32.u64 %0, t; }" : "=r"(a) : "l"(p));
    return a;
}
__device__ __forceinline__ void ldmx4(uint32_t* r, uint32_t addr) {
    asm volatile("ldmatrix.sync.aligned.m8n8.x4.shared.b16 {%0,%1,%2,%3}, [%4];"
                 : "=r"(r[0]), "=r"(r[1]), "=r"(r[2]), "=r"(r[3]) : "r"(addr));
}
__device__ __forceinline__ void mma16816(float* d, const uint32_t* a, uint32_t b0, uint32_t b1) {
    asm volatile("mma.sync.aligned.m16n8k16.row.col.f32.bf16.bf16.f32 "
                 "{%0,%1,%2,%3}, {%4,%5,%6,%7}, {%8,%9}, {%0,%1,%2,%3};"
                 : "+f"(d[0]), "+f"(d[1]), "+f"(d[2]), "+f"(d[3])
                 : "r"(a[0]), "r"(a[1]), "r"(a[2]), "r"(a[3]), "r"(b0), "r"(b1));
}

// ---------------- kernel 1: normalize+scale+split+transpose ------------------
// out[(n*LL+l)*CC+c] = bf16_split( x[n,c,l] * sqrt(10) / max(||x[n,:,l]||, 1e-12) )
__global__ void prep_kernel(const float* __restrict__ rgb, const float* __restrict__ ir) {
    int z = blockIdx.z;
    const float* src = z ? ir : rgb;
    __nv_bfloat16* dhi = z ? g_bbf[0] : g_abf[0];
    __nv_bfloat16* dlo = z ? g_bbf[1] : g_abf[1];
    int n = blockIdx.y;
    int l = blockIdx.x * 256 + threadIdx.x;
    const float* p = src + n * CC * LL + l;

    float x[CC]; float ss = 0.f;
    #pragma unroll
    for (int c = 0; c < CC; ++c) { x[c] = p[c * LL]; ss += x[c] * x[c]; }
    float sc = 3.16227766016838f / fmaxf(sqrtf(ss), 1e-12f);

    unsigned uh[32], ul[32];
    #pragma unroll
    for (int k = 0; k < 32; ++k) {
        float v0 = x[2*k] * sc, v1 = x[2*k+1] * sc;
        __nv_bfloat16 h0 = __float2bfloat16(v0);
        __nv_bfloat16 h1 = __float2bfloat16(v1);
        __nv_bfloat16 l0 = __float2bfloat16(v0 - __bfloat162float(h0));
        __nv_bfloat16 l1 = __float2bfloat16(v1 - __bfloat162float(h1));
        uh[k] = ((unsigned)__bfloat16_as_ushort(h1) << 16) | __bfloat16_as_ushort(h0);
        ul[k] = ((unsigned)__bfloat16_as_ushort(l1) << 16) | __bfloat16_as_ushort(l0);
    }
    size_t ro = (size_t)(n * LL + l) * 8;
    uint4* ph = (uint4*)dhi + ro;
    uint4* pl = (uint4*)dlo + ro;
    #pragma unroll
    for (int k = 0; k < 8; ++k) {
        ph[k] = make_uint4(uh[4*k], uh[4*k+1], uh[4*k+2], uh[4*k+3]);
        pl[k] = make_uint4(ul[4*k], ul[4*k+1], ul[4*k+2], ul[4*k+3]);
    }
}

// ---------------- kernel 2: HMMA (mma.sync) + fused stats --------------------
// D[128x128] = Ahi.Bhi^T + Ahi.Blo^T + Alo.Bhi^T  (fp32 reg accum); logit = exp(D)
#define OA0   0
#define OA1   16384
#define OB0   32768
#define OB1   49152
#define OCK   65536     // u64[8][128] = 8192
#define OCS   73728     // f32[8][128] = 4096
#define ORK   77824     // u64[2][128] = 2048
#define ORS   79872     // f32[2][128] = 1024
#define SMEM_BYTES 80896

__global__ __launch_bounds__(256, 2) void mma_stats_kernel() {
    extern __shared__ __align__(16) char sm[];
    uint32_t sb = smem_u32(sm);

    int tid  = threadIdx.x;
    int lane = tid & 31;
    int wid  = tid >> 5;
    int wm = wid & 3, wn = wid >> 2;          // 4 m-slices x 2 n-slices
    int m0 = wm * 32;
    int n  = blockIdx.y;
    int i0 = blockIdx.x * 128;

    unsigned long long* colkey = (unsigned long long*)(sm + OCK);
    float*              colsum = (float*)(sm + OCS);
    unsigned long long* rowkey = (unsigned long long*)(sm + ORK);
    float*              rowsum = (float*)(sm + ORS);

    // load A tiles (hi+lo): 128 rows x 128B, SW128-swizzled
    {
        const uint4* s0 = (const uint4*)g_abf[0] + (size_t)(n * LL + i0) * 8;
        const uint4* s1 = (const uint4*)g_abf[1] + (size_t)(n * LL + i0) * 8;
        int sub = tid & 7, rb = tid >> 3;
        #pragma unroll
        for (int p = 0; p < 4; ++p) {
            int row = p * 32 + rb;
            uint32_t off = SW128((uint32_t)(row * 128 + sub * 16));
            *(uint4*)(sm + OA0 + off) = s0[row * 8 + sub];
            *(uint4*)(sm + OA1 + off) = s1[row * 8 + sub];
        }
    }

    int lr = lane >> 2, lc2 = (lane & 3) * 2;

    float rm[4], rs[4]; int rj[4];
    #pragma unroll
    for (int r = 0; r < 4; ++r) { rm[r] = 0.f; rs[r] = 0.f; rj[r] = 0; }

    for (int jb = 0; jb < 8; ++jb) {
        int j0 = jb * 128;
        __syncthreads();   // colkey/colsum free, B consumers of prev jb done
        {
            const uint4* s0 = (const uint4*)g_bbf[0] + (size_t)(n * LL + j0) * 8;
            const uint4* s1 = (const uint4*)g_bbf[1] + (size_t)(n * LL + j0) * 8;
            int sub = tid & 7, rb = tid >> 3;
            #pragma unroll
            for (int p = 0; p < 4; ++p) {
                int row = p * 32 + rb;
                uint32_t off = SW128((uint32_t)(row * 128 + sub * 16));
                *(uint4*)(sm + OB0 + off) = s0[row * 8 + sub];
                *(uint4*)(sm + OB1 + off) = s1[row * 8 + sub];
            }
        }
        __syncthreads();

        float acc[2][8][4];
        #pragma unroll
        for (int mt = 0; mt < 2; ++mt)
            #pragma unroll
            for (int nt = 0; nt < 8; ++nt)
                #pragma unroll
                for (int k = 0; k < 4; ++k) acc[mt][nt][k] = 0.f;

        // 3 precision terms: (Ahi,Bhi), (Ahi,Blo), (Alo,Bhi)
        #pragma unroll
        for (int t = 0; t < 3; ++t) {
            uint32_t bA = sb + ((t == 2) ? OA1 : OA0);
            uint32_t bB = sb + ((t == 1) ? OB1 : OB0);
            #pragma unroll
            for (int kk = 0; kk < 4; ++kk) {
                uint32_t afr[2][4], bfr[4][4];
                #pragma unroll
                for (int mt = 0; mt < 2; ++mt) {
                    uint32_t off = SW128((uint32_t)((m0 + mt * 16 + (lane & 15)) * 128
                                                    + kk * 32 + (lane >> 4) * 16));
                    ldmx4(afr[mt], bA + off);
                }
                #pragma unroll
                for (int np = 0; np < 4; ++np) {
                    uint32_t off = SW128((uint32_t)((wn * 64 + np * 16 + (lane & 15)) * 128
                                                    + kk * 32 + (lane >> 4) * 16));
                    ldmx4(bfr[np], bB + off);
                }
                #pragma unroll
                for (int mt = 0; mt < 2; ++mt)
                    #pragma unroll
                    for (int np = 0; np < 4; ++np) {
                        mma16816(acc[mt][2*np],   afr[mt], bfr[np][0], bfr[np][2]);
                        mma16816(acc[mt][2*np+1], afr[mt], bfr[np][1], bfr[np][3]);
                    }
            }
        }

        // ---- epilogue: exp in place + per-thread row stats ----
        #pragma unroll
        for (int mt = 0; mt < 2; ++mt)
            #pragma unroll
            for (int h = 0; h < 2; ++h) {
                int rid = mt * 2 + h;
                #pragma unroll
                for (int nt = 0; nt < 8; ++nt)
                    #pragma unroll
                    for (int e = 0; e < 2; ++e) {
                        float v = __expf(acc[mt][nt][h * 2 + e]);
                        acc[mt][nt][h * 2 + e] = v;
                        rs[rid] += v;
                        int j = j0 + wn * 64 + nt * 8 + lc2 + e;
                        if (v > rm[rid]) { rm[rid] = v; rj[rid] = j; }
                    }
            }

        // ---- col partials: 4 local rows, then 2 shuffle rounds (8 groups) ----
        #pragma unroll
        for (int nt = 0; nt < 8; ++nt)
            #pragma unroll
            for (int e = 0; e < 2; ++e) {
                float v0 = acc[0][nt][e],     v1 = acc[0][nt][2 + e];
                float v2 = acc[1][nt][e],     v3 = acc[1][nt][2 + e];
                float cs = v0; cs += v1; cs += v2; cs += v3;
                float cm = v0; int ri = 0;                 // rows asc: +0,+8,+16,+24
                if (v1 > cm) { cm = v1; ri = 1; }
                if (v2 > cm) { cm = v2; ri = 2; }
                if (v3 > cm) { cm = v3; ri = 3; }
                int grow = i0 + m0 + (ri >> 1) * 16 + (ri & 1) * 8 + lr;
                unsigned long long key =
                    ((unsigned long long)__float_as_uint(cm) << 32) |
                    (unsigned)(0xFFFFFFFFu - (unsigned)grow);
                #pragma unroll
                for (int off = 16; off >= 8; off >>= 1) {
                    unsigned long long ko = __shfl_down_sync(0xffffffffu, key, off);
                    float so = __shfl_down_sync(0xffffffffu, cs, off);
                    cs += so;
                    if (ko > key) key = ko;
                }
                if (lane < 8) {
                    int g = wm * 2 + (lane >> 2);          // 8 groups
                    int col = wn * 64 + nt * 8 + lc2 + e;
                    colkey[g * 128 + col] = key;
                    colsum[g * 128 + col] = cs;
                }
            }
        __syncthreads();
        if (tid < 128) {   // merge 8 group partials in fixed order
            unsigned long long key = colkey[tid];
            float sum = colsum[tid];
            #pragma unroll
            for (int g = 1; g < 8; ++g) {
                unsigned long long ko = colkey[g * 128 + tid];
                if (ko > key) key = ko;
                sum += colsum[g * 128 + tid];
            }
            g_ckey[blockIdx.x][n * LL + j0 + tid] = key;
            g_csum[blockIdx.x][n * LL + j0 + tid] = sum;
        }
    }

    // ---- final row stats: 4-lane tree over lc, then 2-way wn merge ----
    #pragma unroll
    for (int off = 2; off >= 1; off >>= 1) {
        #pragma unroll
        for (int r = 0; r < 4; ++r) {
            float mo = __shfl_down_sync(0xffffffffu, rm[r], off);
            int   jo = __shfl_down_sync(0xffffffffu, rj[r], off);
            float so = __shfl_down_sync(0xffffffffu, rs[r], off);
            rs[r] += so;
            if (mo > rm[r] || (mo == rm[r] && jo < rj[r])) { rm[r] = mo; rj[r] = jo; }
        }
    }
    __syncthreads();   // colkey merge done; rowkey region free
    if ((lane & 3) == 0) {
        #pragma unroll
        for (int r = 0; r < 4; ++r) {
            int row = m0 + (r >> 1) * 16 + (r & 1) * 8 + lr;
            rowkey[wn * 128 + row] =
                ((unsigned long long)__float_as_uint(rm[r]) << 32) |
                (unsigned)(0xFFFFFFFFu - (unsigned)rj[r]);
            rowsum[wn * 128 + row] = rs[r];
        }
    }
    __syncthreads();
    if (tid < 128) {
        unsigned long long k0 = rowkey[tid], k1 = rowkey[128 + tid];
        float s = rowsum[tid] + rowsum[128 + tid];
        unsigned long long k = (k1 > k0) ? k1 : k0;
        int gi = n * LL + i0 + tid;
        g_max[0][gi] = __uint_as_float((unsigned)(k >> 32));
        g_arg[0][gi] = (int)(0xFFFFFFFFu - (unsigned)(k & 0xFFFFFFFFu)) & (LL - 1);
        g_sum[0][gi] = s;
    }
}

// ---------------- kernel 3: fused colmerge + per-entry -log terms ------------
// reference: max_h/(sum_h + eps) * max_o[arg_h] / (sum_o + eps); sum_o at OWN index.
// Col stats are merged inline from the 8 per-panel partials (fixed order).
__global__ void loss_part_kernel() {   // grid 256, block 256: 1 entry/thread
    int ee = blockIdx.x * 256 + threadIdx.x;   // 0..65535
    int half = ee >> 15;                       // 0: rgb2ir2rgb, 1: ir2rgb2ir
    int idx  = ee & 32767;                     // n*L + l
    int base = idx & ~(LL - 1);
    float mp, sp, mo, so;

    if (half == 0) {
        mp = g_max[0][idx]; sp = g_sum[0][idx];
        int a = g_arg[0][idx];
        unsigned long long key = g_ckey[0][base + a];   // col max at gathered index
        float cs = g_csum[0][idx];                       // col sum at own index
        #pragma unroll
        for (int b = 1; b < 8; ++b) {
            unsigned long long ko = g_ckey[b][base + a];
            if (ko > key) key = ko;
            cs += g_csum[b][idx];
        }
        mo = __uint_as_float((unsigned)(key >> 32));
        so = cs;
    } else {
        unsigned long long key = g_ckey[0][idx];         // own col stats
        float cs = g_csum[0][idx];
        #pragma unroll
        for (int b = 1; b < 8; ++b) {
            unsigned long long ko = g_ckey[b][idx];
            if (ko > key) key = ko;
            cs += g_csum[b][idx];
        }
        mp = __uint_as_float((unsigned)(key >> 32));
        sp = cs;
        int a = (int)(0xFFFFFFFFu - (unsigned)(key & 0xFFFFFFFFu)) & (LL - 1);
        mo = g_max[0][base + a];
        so = g_sum[0][idx];
    }
    float acc = __logf(mp / (sp + EPS) * (mo / (so + EPS)));

    __shared__ float red[256];
    red[threadIdx.x] = acc;
    __syncthreads();
    for (int st = 128; st; st >>= 1) {
        if (threadIdx.x < st) red[threadIdx.x] += red[threadIdx.x + st];
        __syncthreads();
    }
    if (threadIdx.x == 0) g_part[blockIdx.x] = red[0];
}

__global__ void loss_final_kernel(float* __restrict__ out) {
    __shared__ float red[256];
    red[threadIdx.x] = g_part[threadIdx.x];
    __syncthreads();
    for (int st = 128; st; st >>= 1) {
        if (threadIdx.x < st) red[threadIdx.x] += red[threadIdx.x + st];
        __syncthreads();
    }
    if (threadIdx.x == 0) out[0] = -red[0] * (1.0f / 65536.0f);
}

// ---------------- launch ------------------------------------------------------
extern "C" void kernel_launch(void* const* d_in, const int* in_sizes, int n_in,
                              void* d_out, int out_size) {
    const float* rgb = (const float*)d_in[0];
    const float* ir  = (const float*)d_in[1];

    cudaFuncSetAttribute(mma_stats_kernel,
                         cudaFuncAttributeMaxDynamicSharedMemorySize, SMEM_BYTES);

    prep_kernel<<<dim3(4, 32, 2), 256>>>(rgb, ir);
    mma_stats_kernel<<<dim3(8, 32), 256, SMEM_BYTES>>>();
    loss_part_kernel<<<256, 256>>>();
    loss_final_kernel<<<1, 256>>>((float*)d_out);
}

// round 13
// speedup vs baseline: 4.4327x; 1.7915x over previous
#include <cuda_runtime.h>
#include <cuda_fp16.h>
#include <math.h>
#include <stdint.h>

#define NB   32
#define CC   64
#define LL   1024
#define EPS  1e-6f

// ---------------- scratch (static __device__, no allocation) ----------------
__device__ __half g_ah[NB*LL*CC];                // rgb * (sqrt10/||.||), [ (n*LL+l)*CC+c ]
__device__ __half g_bh[NB*LL*CC];                // ir  * (sqrt10/||.||)
__device__ float g_max[NB*LL];                   // row stats
__device__ float g_sum[NB*LL];
__device__ int   g_arg[NB*LL];
__device__ unsigned long long g_ckey[8][NB*LL];  // per-panel col (max,arg) packed
__device__ float              g_csum[8][NB*LL];  // per-panel col sums
__device__ float g_part[256];

#define SW128(o) ((o) ^ (((o) >> 3) & 0x70))

__device__ __forceinline__ uint32_t smem_u32(const void* p) {
    uint32_t a;
    asm("{ .reg .u64 t; cvta.to.shared.u64 t, %1; cvt.u32.u64 %0, t; }" : "=r"(a) : "l"(p));
    return a;
}
__device__ __forceinline__ void ldmx4(uint32_t* r, uint32_t addr) {
    asm volatile("ldmatrix.sync.aligned.m8n8.x4.shared.b16 {%0,%1,%2,%3}, [%4];"
                 : "=r"(r[0]), "=r"(r[1]), "=r"(r[2]), "=r"(r[3]) : "r"(addr));
}
__device__ __forceinline__ void mma16816(float* d, const uint32_t* a, uint32_t b0, uint32_t b1) {
    asm volatile("mma.sync.aligned.m16n8k16.row.col.f32.f16.f16.f32 "
                 "{%0,%1,%2,%3}, {%4,%5,%6,%7}, {%8,%9}, {%0,%1,%2,%3};"
                 : "+f"(d[0]), "+f"(d[1]), "+f"(d[2]), "+f"(d[3])
                 : "r"(a[0]), "r"(a[1]), "r"(a[2]), "r"(a[3]), "r"(b0), "r"(b1));
}

// ---------------- kernel 1: normalize+scale+fp16+transpose -------------------
// out[(n*LL+l)*CC+c] = fp16( x[n,c,l] * sqrt(10) / max(||x[n,:,l]||, 1e-12) )
__global__ void prep_kernel(const float* __restrict__ rgb, const float* __restrict__ ir) {
    int z = blockIdx.z;
    const float* src = z ? ir : rgb;
    __half* dst = z ? g_bh : g_ah;
    int n = blockIdx.y;
    int l = blockIdx.x * 256 + threadIdx.x;
    const float* p = src + n * CC * LL + l;

    float x[CC]; float ss = 0.f;
    #pragma unroll
    for (int c = 0; c < CC; ++c) { float v = p[c * LL]; x[c] = v; ss += v * v; }
    float sc = 3.16227766016838f / fmaxf(sqrtf(ss), 1e-12f);

    unsigned u[32];
    #pragma unroll
    for (int k = 0; k < 32; ++k) {
        __half2 h2 = __floats2half2_rn(x[2*k] * sc, x[2*k+1] * sc);
        u[k] = *reinterpret_cast<unsigned*>(&h2);
    }
    uint4* pd = (uint4*)dst + (size_t)(n * LL + l) * 8;
    #pragma unroll
    for (int k = 0; k < 8; ++k)
        pd[k] = make_uint4(u[4*k], u[4*k+1], u[4*k+2], u[4*k+3]);
}

// ---------------- kernel 2: HMMA (mma.sync fp16) + fused stats ---------------
// D[128x128] = A.B^T (fp32 reg accum); logit = exp(D)
#define OA    0         // 16384
#define OB    16384     // 16384
#define OCK   32768     // u64[8][128] = 8192
#define OCS   40960     // f32[8][128] = 4096
#define ORK   45056     // u64[2][128] = 2048
#define ORS   47104     // f32[2][128] = 1024
#define SMEM_BYTES 48128

__global__ __launch_bounds__(256, 2) void mma_stats_kernel() {
    extern __shared__ __align__(16) char sm[];
    uint32_t sb = smem_u32(sm);

    int tid  = threadIdx.x;
    int lane = tid & 31;
    int wid  = tid >> 5;
    int wm = wid & 3, wn = wid >> 2;          // 4 m-slices x 2 n-slices
    int m0 = wm * 32;
    int n  = blockIdx.y;
    int i0 = blockIdx.x * 128;

    unsigned long long* colkey = (unsigned long long*)(sm + OCK);
    float*              colsum = (float*)(sm + OCS);
    unsigned long long* rowkey = (unsigned long long*)(sm + ORK);
    float*              rowsum = (float*)(sm + ORS);

    // load A tile: 128 rows x 128B, SW128-swizzled
    {
        const uint4* s0 = (const uint4*)g_ah + (size_t)(n * LL + i0) * 8;
        int sub = tid & 7, rb = tid >> 3;
        #pragma unroll
        for (int p = 0; p < 4; ++p) {
            int row = p * 32 + rb;
            uint32_t off = SW128((uint32_t)(row * 128 + sub * 16));
            *(uint4*)(sm + OA + off) = s0[row * 8 + sub];
        }
    }

    int lr = lane >> 2, lc2 = (lane & 3) * 2;

    float rm[4], rs[4]; int rj[4];
    #pragma unroll
    for (int r = 0; r < 4; ++r) { rm[r] = 0.f; rs[r] = 0.f; rj[r] = 0; }

    for (int jb = 0; jb < 8; ++jb) {
        int j0 = jb * 128;
        __syncthreads();   // colkey/colsum free, B consumers of prev jb done
        {
            const uint4* s0 = (const uint4*)g_bh + (size_t)(n * LL + j0) * 8;
            int sub = tid & 7, rb = tid >> 3;
            #pragma unroll
            for (int p = 0; p < 4; ++p) {
                int row = p * 32 + rb;
                uint32_t off = SW128((uint32_t)(row * 128 + sub * 16));
                *(uint4*)(sm + OB + off) = s0[row * 8 + sub];
            }
        }
        __syncthreads();

        float acc[2][8][4];
        #pragma unroll
        for (int mt = 0; mt < 2; ++mt)
            #pragma unroll
            for (int nt = 0; nt < 8; ++nt)
                #pragma unroll
                for (int k = 0; k < 4; ++k) acc[mt][nt][k] = 0.f;

        #pragma unroll
        for (int kk = 0; kk < 4; ++kk) {
            uint32_t afr[2][4], bfr[4][4];
            #pragma unroll
            for (int mt = 0; mt < 2; ++mt) {
                uint32_t off = SW128((uint32_t)((m0 + mt * 16 + (lane & 15)) * 128
                                                + kk * 32 + (lane >> 4) * 16));
                ldmx4(afr[mt], sb + OA + off);
            }
            #pragma unroll
            for (int np = 0; np < 4; ++np) {
                uint32_t off = SW128((uint32_t)((wn * 64 + np * 16 + (lane & 15)) * 128
                                                + kk * 32 + (lane >> 4) * 16));
                ldmx4(bfr[np], sb + OB + off);
            }
            #pragma unroll
            for (int mt = 0; mt < 2; ++mt)
                #pragma unroll
                for (int np = 0; np < 4; ++np) {
                    mma16816(acc[mt][2*np],   afr[mt], bfr[np][0], bfr[np][2]);
                    mma16816(acc[mt][2*np+1], afr[mt], bfr[np][1], bfr[np][3]);
                }
        }

        // ---- epilogue: exp in place + per-thread row stats ----
        #pragma unroll
        for (int mt = 0; mt < 2; ++mt)
            #pragma unroll
            for (int h = 0; h < 2; ++h) {
                int rid = mt * 2 + h;
                #pragma unroll
                for (int nt = 0; nt < 8; ++nt)
                    #pragma unroll
                    for (int e = 0; e < 2; ++e) {
                        float v = __expf(acc[mt][nt][h * 2 + e]);
                        acc[mt][nt][h * 2 + e] = v;
                        rs[rid] += v;
                        int j = j0 + wn * 64 + nt * 8 + lc2 + e;
                        if (v > rm[rid]) { rm[rid] = v; rj[rid] = j; }
                    }
            }

        // ---- col partials: 4 local rows, then 2 shuffle rounds (8 groups) ----
        #pragma unroll
        for (int nt = 0; nt < 8; ++nt)
            #pragma unroll
            for (int e = 0; e < 2; ++e) {
                float v0 = acc[0][nt][e],     v1 = acc[0][nt][2 + e];
                float v2 = acc[1][nt][e],     v3 = acc[1][nt][2 + e];
                float cs = v0; cs += v1; cs += v2; cs += v3;
                float cm = v0; int ri = 0;                 // rows asc: +0,+8,+16,+24
                if (v1 > cm) { cm = v1; ri = 1; }
                if (v2 > cm) { cm = v2; ri = 2; }
                if (v3 > cm) { cm = v3; ri = 3; }
                int grow = i0 + m0 + (ri >> 1) * 16 + (ri & 1) * 8 + lr;
                unsigned long long key =
                    ((unsigned long long)__float_as_uint(cm) << 32) |
                    (unsigned)(0xFFFFFFFFu - (unsigned)grow);
                #pragma unroll
                for (int off = 16; off >= 8; off >>= 1) {
                    unsigned long long ko = __shfl_down_sync(0xffffffffu, key, off);
                    float so = __shfl_down_sync(0xffffffffu, cs, off);
                    cs += so;
                    if (ko > key) key = ko;
                }
                if (lane < 8) {
                    int g = wm * 2 + (lane >> 2);          // 8 groups
                    int col = wn * 64 + nt * 8 + lc2 + e;
                    colkey[g * 128 + col] = key;
                    colsum[g * 128 + col] = cs;
                }
            }
        __syncthreads();
        if (tid < 128) {   // merge 8 group partials in fixed order
            unsigned long long key = colkey[tid];
            float sum = colsum[tid];
            #pragma unroll
            for (int g = 1; g < 8; ++g) {
                unsigned long long ko = colkey[g * 128 + tid];
                if (ko > key) key = ko;
                sum += colsum[g * 128 + tid];
            }
            g_ckey[blockIdx.x][n * LL + j0 + tid] = key;
            g_csum[blockIdx.x][n * LL + j0 + tid] = sum;
        }
    }

    // ---- final row stats: 4-lane tree over lc, then 2-way wn merge ----
    #pragma unroll
    for (int off = 2; off >= 1; off >>= 1) {
        #pragma unroll
        for (int r = 0; r < 4; ++r) {
            float mo = __shfl_down_sync(0xffffffffu, rm[r], off);
            int   jo = __shfl_down_sync(0xffffffffu, rj[r], off);
            float so = __shfl_down_sync(0xffffffffu, rs[r], off);
            rs[r] += so;
            if (mo > rm[r] || (mo == rm[r] && jo < rj[r])) { rm[r] = mo; rj[r] = jo; }
        }
    }
    __syncthreads();   // colkey merge done; rowkey region free
    if ((lane & 3) == 0) {
        #pragma unroll
        for (int r = 0; r < 4; ++r) {
            int row = m0 + (r >> 1) * 16 + (r & 1) * 8 + lr;
            rowkey[wn * 128 + row] =
                ((unsigned long long)__float_as_uint(rm[r]) << 32) |
                (unsigned)(0xFFFFFFFFu - (unsigned)rj[r]);
            rowsum[wn * 128 + row] = rs[r];
        }
    }
    __syncthreads();
    if (tid < 128) {
        unsigned long long k0 = rowkey[tid], k1 = rowkey[128 + tid];
        float s = rowsum[tid] + rowsum[128 + tid];
        unsigned long long k = (k1 > k0) ? k1 : k0;
        int gi = n * LL + i0 + tid;
        g_max[gi] = __uint_as_float((unsigned)(k >> 32));
        g_arg[gi] = (int)(0xFFFFFFFFu - (unsigned)(k & 0xFFFFFFFFu)) & (LL - 1);
        g_sum[gi] = s;
    }
}

// ---------------- kernel 3: fused colmerge + per-entry -log terms ------------
// reference: max_h/(sum_h + eps) * max_o[arg_h] / (sum_o + eps); sum_o at OWN index.
__global__ void loss_part_kernel() {   // grid 256, block 256: 1 entry/thread
    int ee = blockIdx.x * 256 + threadIdx.x;   // 0..65535
    int half = ee >> 15;                       // 0: rgb2ir2rgb, 1: ir2rgb2ir
    int idx  = ee & 32767;                     // n*L + l
    int base = idx & ~(LL - 1);
    float mp, sp, mo, so;

    if (half == 0) {
        mp = g_max[idx]; sp = g_sum[idx];
        int a = g_arg[idx];
        unsigned long long key = g_ckey[0][base + a];   // col max at gathered index
        float cs = g_csum[0][idx];                       // col sum at own index
        #pragma unroll
        for (int b = 1; b < 8; ++b) {
            unsigned long long ko = g_ckey[b][base + a];
            if (ko > key) key = ko;
            cs += g_csum[b][idx];
        }
        mo = __uint_as_float((unsigned)(key >> 32));
        so = cs;
    } else {
        unsigned long long key = g_ckey[0][idx];         // own col stats
        float cs = g_csum[0][idx];
        #pragma unroll
        for (int b = 1; b < 8; ++b) {
            unsigned long long ko = g_ckey[b][idx];
            if (ko > key) key = ko;
            cs += g_csum[b][idx];
        }
        mp = __uint_as_float((unsigned)(key >> 32));
        sp = cs;
        int a = (int)(0xFFFFFFFFu - (unsigned)(key & 0xFFFFFFFFu)) & (LL - 1);
        mo = g_max[base + a];
        so = g_sum[idx];
    }
    float acc = __logf(mp / (sp + EPS) * (mo / (so + EPS)));

    __shared__ float red[256];
    red[threadIdx.x] = acc;
    __syncthreads();
    for (int st = 128; st; st >>= 1) {
        if (threadIdx.x < st) red[threadIdx.x] += red[threadIdx.x + st];
        __syncthreads();
    }
    if (threadIdx.x == 0) g_part[blockIdx.x] = red[0];
}

__global__ void loss_final_kernel(float* __restrict__ out) {
    __shared__ float red[256];
    red[threadIdx.x] = g_part[threadIdx.x];
    __syncthreads();
    for (int st = 128; st; st >>= 1) {
        if (threadIdx.x < st) red[threadIdx.x] += red[threadIdx.x + st];
        __syncthreads();
    }
    if (threadIdx.x == 0) out[0] = -red[0] * (1.0f / 65536.0f);
}

// ---------------- launch ------------------------------------------------------
extern "C" void kernel_launch(void* const* d_in, const int* in_sizes, int n_in,
                              void* d_out, int out_size) {
    const float* rgb = (const float*)d_in[0];
    const float* ir  = (const float*)d_in[1];

    cudaFuncSetAttribute(mma_stats_kernel,
                         cudaFuncAttributeMaxDynamicSharedMemorySize, SMEM_BYTES);

    prep_kernel<<<dim3(4, 32, 2), 256>>>(rgb, ir);
    mma_stats_kernel<<<dim3(8, 32), 256, SMEM_BYTES>>>();
    loss_part_kernel<<<256, 256>>>();
    loss_final_kernel<<<1, 256>>>((float*)d_out);
}

// round 14
// speedup vs baseline: 4.7282x; 1.0667x over previous
#include <cuda_runtime.h>
#include <cuda_fp16.h>
#include <math.h>
#include <stdint.h>

#define NB   32
#define CC   64
#define LL   1024
#define EPS  1e-6f

// ---------------- scratch (static __device__, no allocation) ----------------
__device__ __half g_ah[NB*LL*CC];                // rgb * (sqrt(10*log2e)/||.||)
__device__ __half g_bh[NB*LL*CC];                // ir  * (sqrt(10*log2e)/||.||)
__device__ unsigned long long g_rkey[4][NB*LL];  // per-quarter row (max,arg) packed
__device__ float              g_rsum[4][NB*LL];  // per-quarter row sums
__device__ unsigned long long g_ckey[8][NB*LL];  // per-panel col (max,arg) packed
__device__ float              g_csum[8][NB*LL];  // per-panel col sums
__device__ float g_part[256];
__device__ unsigned g_cnt;

#define SW128(o) ((o) ^ (((o) >> 3) & 0x70))

__device__ __forceinline__ uint32_t smem_u32(const void* p) {
    uint32_t a;
    asm("{ .reg .u64 t; cvta.to.shared.u64 t, %1; cvt.u32.u64 %0, t; }" : "=r"(a) : "l"(p));
    return a;
}
__device__ __forceinline__ float ex2f(float x) {
    float y; asm("ex2.approx.f32 %0, %1;" : "=f"(y) : "f"(x)); return y;
}
__device__ __forceinline__ void ldmx4(uint32_t* r, uint32_t addr) {
    asm volatile("ldmatrix.sync.aligned.m8n8.x4.shared.b16 {%0,%1,%2,%3}, [%4];"
                 : "=r"(r[0]), "=r"(r[1]), "=r"(r[2]), "=r"(r[3]) : "r"(addr));
}
__device__ __forceinline__ void mma16816(float* d, const uint32_t* a, uint32_t b0, uint32_t b1) {
    asm volatile("mma.sync.aligned.m16n8k16.row.col.f32.f16.f16.f32 "
                 "{%0,%1,%2,%3}, {%4,%5,%6,%7}, {%8,%9}, {%0,%1,%2,%3};"
                 : "+f"(d[0]), "+f"(d[1]), "+f"(d[2]), "+f"(d[3])
                 : "r"(a[0]), "r"(a[1]), "r"(a[2]), "r"(a[3]), "r"(b0), "r"(b1));
}

// ---------------- kernel 1: normalize+scale+fp16+transpose -------------------
// scale folds sqrt(10 * log2(e)) so the logit exponent is already in log2 domain:
// 2^(dot) == exp(dot_orig / TEMP)
__global__ void prep_kernel(const float* __restrict__ rgb, const float* __restrict__ ir) {
    int z = blockIdx.z;
    const float* src = z ? ir : rgb;
    __half* dst = z ? g_bh : g_ah;
    int n = blockIdx.y;
    int l = blockIdx.x * 256 + threadIdx.x;
    const float* p = src + n * CC * LL + l;

    float x[CC]; float ss = 0.f;
    #pragma unroll
    for (int c = 0; c < CC; ++c) { float v = p[c * LL]; x[c] = v; ss += v * v; }
    float sc = 3.79828262f / fmaxf(sqrtf(ss), 1e-12f);   // sqrt(10*log2(e))

    unsigned u[32];
    #pragma unroll
    for (int k = 0; k < 32; ++k) {
        __half2 h2 = __floats2half2_rn(x[2*k] * sc, x[2*k+1] * sc);
        u[k] = *reinterpret_cast<unsigned*>(&h2);
    }
    uint4* pd = (uint4*)dst + (size_t)(n * LL + l) * 8;
    #pragma unroll
    for (int k = 0; k < 8; ++k)
        pd[k] = make_uint4(u[4*k], u[4*k+1], u[4*k+2], u[4*k+3]);
}

// ---------------- kernel 2: HMMA (mma.sync fp16) + fused stats ---------------
// grid (8 i-panels, 32 n, 4 j-quarters); each CTA: 128 rows x 256 cols (2 jb)
#define OA    0         // 16384
#define OB    16384     // 16384
#define OCK   32768     // u64[8][128] = 8192
#define OCS   40960     // f32[8][128] = 4096
#define ORK   45056     // u64[2][128] = 2048
#define ORS   47104     // f32[2][128] = 1024
#define SMEM_BYTES 48128

__global__ __launch_bounds__(256, 2) void mma_stats_kernel() {
    extern __shared__ __align__(16) char sm[];
    uint32_t sb = smem_u32(sm);

    int tid  = threadIdx.x;
    int lane = tid & 31;
    int wid  = tid >> 5;
    int wm = wid & 3, wn = wid >> 2;          // 4 m-slices x 2 n-slices
    int m0 = wm * 32;
    int n  = blockIdx.y;
    int i0 = blockIdx.x * 128;
    int qz = blockIdx.z;                      // j-quarter: jb = qz*2 + {0,1}

    unsigned long long* colkey = (unsigned long long*)(sm + OCK);
    float*              colsum = (float*)(sm + OCS);
    unsigned long long* rowkey = (unsigned long long*)(sm + ORK);
    float*              rowsum = (float*)(sm + ORS);

    // load A tile: 128 rows x 128B, SW128-swizzled
    {
        const uint4* s0 = (const uint4*)g_ah + (size_t)(n * LL + i0) * 8;
        int sub = tid & 7, rb = tid >> 3;
        #pragma unroll
        for (int p = 0; p < 4; ++p) {
            int row = p * 32 + rb;
            uint32_t off = SW128((uint32_t)(row * 128 + sub * 16));
            *(uint4*)(sm + OA + off) = s0[row * 8 + sub];
        }
    }

    int lr = lane >> 2, lc2 = (lane & 3) * 2;

    float rm[4], rs[4]; int rj[4];
    #pragma unroll
    for (int r = 0; r < 4; ++r) { rm[r] = 0.f; rs[r] = 0.f; rj[r] = 0; }

    for (int jb = 0; jb < 2; ++jb) {
        int j0 = (qz * 2 + jb) * 128;
        __syncthreads();   // colkey/colsum free, B consumers of prev jb done
        {
            const uint4* s0 = (const uint4*)g_bh + (size_t)(n * LL + j0) * 8;
            int sub = tid & 7, rb = tid >> 3;
            #pragma unroll
            for (int p = 0; p < 4; ++p) {
                int row = p * 32 + rb;
                uint32_t off = SW128((uint32_t)(row * 128 + sub * 16));
                *(uint4*)(sm + OB + off) = s0[row * 8 + sub];
            }
        }
        __syncthreads();

        float acc[2][8][4];
        #pragma unroll
        for (int mt = 0; mt < 2; ++mt)
            #pragma unroll
            for (int nt = 0; nt < 8; ++nt)
                #pragma unroll
                for (int k = 0; k < 4; ++k) acc[mt][nt][k] = 0.f;

        #pragma unroll
        for (int kk = 0; kk < 4; ++kk) {
            uint32_t afr[2][4], bfr[4][4];
            #pragma unroll
            for (int mt = 0; mt < 2; ++mt) {
                uint32_t off = SW128((uint32_t)((m0 + mt * 16 + (lane & 15)) * 128
                                                + kk * 32 + (lane >> 4) * 16));
                ldmx4(afr[mt], sb + OA + off);
            }
            #pragma unroll
            for (int np = 0; np < 4; ++np) {
                uint32_t off = SW128((uint32_t)((wn * 64 + np * 16 + (lane & 15)) * 128
                                                + kk * 32 + (lane >> 4) * 16));
                ldmx4(bfr[np], sb + OB + off);
            }
            #pragma unroll
            for (int mt = 0; mt < 2; ++mt)
                #pragma unroll
                for (int np = 0; np < 4; ++np) {
                    mma16816(acc[mt][2*np],   afr[mt], bfr[np][0], bfr[np][2]);
                    mma16816(acc[mt][2*np+1], afr[mt], bfr[np][1], bfr[np][3]);
                }
        }

        // ---- epilogue: 2^x in place + per-thread row stats ----
        #pragma unroll
        for (int mt = 0; mt < 2; ++mt)
            #pragma unroll
            for (int h = 0; h < 2; ++h) {
                int rid = mt * 2 + h;
                #pragma unroll
                for (int nt = 0; nt < 8; ++nt)
                    #pragma unroll
                    for (int e = 0; e < 2; ++e) {
                        float v = ex2f(acc[mt][nt][h * 2 + e]);
                        acc[mt][nt][h * 2 + e] = v;
                        rs[rid] += v;
                        int j = j0 + wn * 64 + nt * 8 + lc2 + e;
                        if (v > rm[rid]) { rm[rid] = v; rj[rid] = j; }
                    }
            }

        // ---- col partials: 4 local rows, then 2 shuffle rounds (8 groups) ----
        #pragma unroll
        for (int nt = 0; nt < 8; ++nt)
            #pragma unroll
            for (int e = 0; e < 2; ++e) {
                float v0 = acc[0][nt][e],     v1 = acc[0][nt][2 + e];
                float v2 = acc[1][nt][e],     v3 = acc[1][nt][2 + e];
                float cs = v0; cs += v1; cs += v2; cs += v3;
                float cm = v0; int ri = 0;                 // rows asc: +0,+8,+16,+24
                if (v1 > cm) { cm = v1; ri = 1; }
                if (v2 > cm) { cm = v2; ri = 2; }
                if (v3 > cm) { cm = v3; ri = 3; }
                int grow = i0 + m0 + (ri >> 1) * 16 + (ri & 1) * 8 + lr;
                unsigned long long key =
                    ((unsigned long long)__float_as_uint(cm) << 32) |
                    (unsigned)(0xFFFFFFFFu - (unsigned)grow);
                #pragma unroll
                for (int off = 16; off >= 8; off >>= 1) {
                    unsigned long long ko = __shfl_down_sync(0xffffffffu, key, off);
                    float so = __shfl_down_sync(0xffffffffu, cs, off);
                    cs += so;
                    if (ko > key) key = ko;
                }
                if (lane < 8) {
                    int g = wm * 2 + (lane >> 2);          // 8 groups
                    int col = wn * 64 + nt * 8 + lc2 + e;
                    colkey[g * 128 + col] = key;
                    colsum[g * 128 + col] = cs;
                }
            }
        __syncthreads();
        if (tid < 128) {   // merge 8 group partials in fixed order
            unsigned long long key = colkey[tid];
            float sum = colsum[tid];
            #pragma unroll
            for (int g = 1; g < 8; ++g) {
                unsigned long long ko = colkey[g * 128 + tid];
                if (ko > key) key = ko;
                sum += colsum[g * 128 + tid];
            }
            g_ckey[blockIdx.x][n * LL + j0 + tid] = key;
            g_csum[blockIdx.x][n * LL + j0 + tid] = sum;
        }
    }

    // ---- row partials for this quarter: 4-lane tree, wn merge, write --------
    #pragma unroll
    for (int off = 2; off >= 1; off >>= 1) {
        #pragma unroll
        for (int r = 0; r < 4; ++r) {
            float mo = __shfl_down_sync(0xffffffffu, rm[r], off);
            int   jo = __shfl_down_sync(0xffffffffu, rj[r], off);
            float so = __shfl_down_sync(0xffffffffu, rs[r], off);
            rs[r] += so;
            if (mo > rm[r] || (mo == rm[r] && jo < rj[r])) { rm[r] = mo; rj[r] = jo; }
        }
    }
    __syncthreads();   // colkey merge done; rowkey region free
    if ((lane & 3) == 0) {
        #pragma unroll
        for (int r = 0; r < 4; ++r) {
            int row = m0 + (r >> 1) * 16 + (r & 1) * 8 + lr;
            rowkey[wn * 128 + row] =
                ((unsigned long long)__float_as_uint(rm[r]) << 32) |
                (unsigned)(0xFFFFFFFFu - (unsigned)rj[r]);
            rowsum[wn * 128 + row] = rs[r];
        }
    }
    __syncthreads();
    if (tid < 128) {
        unsigned long long k0 = rowkey[tid], k1 = rowkey[128 + tid];
        float s = rowsum[tid] + rowsum[128 + tid];
        unsigned long long k = (k1 > k0) ? k1 : k0;
        int gi = n * LL + i0 + tid;
        g_rkey[qz][gi] = k;
        g_rsum[qz][gi] = s;
    }
}

// ---------------- kernel 3: merge partials + -log terms + final reduce -------
// reference: max_h/(sum_h + eps) * max_o[arg_h] / (sum_o + eps); sum_o at OWN index.
__device__ __forceinline__ unsigned long long row_key(int i) {
    unsigned long long key = g_rkey[0][i];
    #pragma unroll
    for (int q = 1; q < 4; ++q) { unsigned long long k = g_rkey[q][i]; if (k > key) key = k; }
    return key;
}
__device__ __forceinline__ float row_sum(int i) {
    float s = g_rsum[0][i];
    #pragma unroll
    for (int q = 1; q < 4; ++q) s += g_rsum[q][i];
    return s;
}
__device__ __forceinline__ unsigned long long col_key(int i) {
    unsigned long long key = g_ckey[0][i];
    #pragma unroll
    for (int b = 1; b < 8; ++b) { unsigned long long k = g_ckey[b][i]; if (k > key) key = k; }
    return key;
}
__device__ __forceinline__ float col_sum(int i) {
    float s = g_csum[0][i];
    #pragma unroll
    for (int b = 1; b < 8; ++b) s += g_csum[b][i];
    return s;
}

__global__ void loss_kernel(float* __restrict__ out) {   // grid 256 x 256
    int ee = blockIdx.x * 256 + threadIdx.x;   // 0..65535
    int half = ee >> 15;                       // 0: rgb2ir2rgb, 1: ir2rgb2ir
    int idx  = ee & 32767;                     // n*L + l
    int base = idx & ~(LL - 1);
    float mp, sp, mo, so;

    if (half == 0) {
        unsigned long long rk = row_key(idx);
        mp = __uint_as_float((unsigned)(rk >> 32));
        sp = row_sum(idx);
        int a = (int)(0xFFFFFFFFu - (unsigned)(rk & 0xFFFFFFFFu)) & (LL - 1);
        mo = __uint_as_float((unsigned)(col_key(base + a) >> 32));
        so = col_sum(idx);
    } else {
        unsigned long long ck = col_key(idx);
        mp = __uint_as_float((unsigned)(ck >> 32));
        sp = col_sum(idx);
        int a = (int)(0xFFFFFFFFu - (unsigned)(ck & 0xFFFFFFFFu)) & (LL - 1);
        mo = __uint_as_float((unsigned)(row_key(base + a) >> 32));
        so = row_sum(idx);
    }
    float acc = __logf(mp / (sp + EPS) * (mo / (so + EPS)));

    __shared__ float red[256];
    __shared__ unsigned is_last;
    red[threadIdx.x] = acc;
    __syncthreads();
    for (int st = 128; st; st >>= 1) {
        if (threadIdx.x < st) red[threadIdx.x] += red[threadIdx.x + st];
        __syncthreads();
    }
    if (threadIdx.x == 0) {
        g_part[blockIdx.x] = red[0];
        __threadfence();
        is_last = (atomicAdd(&g_cnt, 1u) == 255u) ? 1u : 0u;
    }
    __syncthreads();
    if (is_last) {
        __threadfence();
        red[threadIdx.x] = __ldcg(&g_part[threadIdx.x]);
        __syncthreads();
        for (int st = 128; st; st >>= 1) {
            if (threadIdx.x < st) red[threadIdx.x] += red[threadIdx.x + st];
            __syncthreads();
        }
        if (threadIdx.x == 0) {
            out[0] = -red[0] * (1.0f / 65536.0f);
            g_cnt = 0;                      // reset for graph replay
        }
    }
}

// ---------------- launch ------------------------------------------------------
extern "C" void kernel_launch(void* const* d_in, const int* in_sizes, int n_in,
                              void* d_out, int out_size) {
    const float* rgb = (const float*)d_in[0];
    const float* ir  = (const float*)d_in[1];

    cudaFuncSetAttribute(mma_stats_kernel,
                         cudaFuncAttributeMaxDynamicSharedMemorySize, SMEM_BYTES);

    prep_kernel<<<dim3(4, 32, 2), 256>>>(rgb, ir);
    mma_stats_kernel<<<dim3(8, 32, 4), 256, SMEM_BYTES>>>();
    loss_kernel<<<256, 256>>>((float*)d_out);
}

// round 15
// speedup vs baseline: 4.7958x; 1.0143x over previous
#include <cuda_runtime.h>
#include <cuda_fp16.h>
#include <math.h>
#include <stdint.h>

#define NB   32
#define CC   64
#define LL   1024
#define EPS  1e-6f

// ---------------- scratch (static __device__, no allocation) ----------------
__device__ __half g_ah[NB*LL*CC];                // rgb * (sqrt(10*log2e)/||.||)
__device__ __half g_bh[NB*LL*CC];                // ir  * (sqrt(10*log2e)/||.||)
__device__ unsigned long long g_rkey[4][NB*LL];  // per-quarter row (max,arg) packed
__device__ float              g_rsum[4][NB*LL];  // per-quarter row sums
__device__ unsigned long long g_ckey[8][NB*LL];  // per-panel col (max,arg) packed
__device__ float              g_csum[8][NB*LL];  // per-panel col sums
__device__ float g_part[256];
__device__ unsigned g_cnt;

#define SW128(o) ((o) ^ (((o) >> 3) & 0x70))

__device__ __forceinline__ uint32_t smem_u32(const void* p) {
    uint32_t a;
    asm("{ .reg .u64 t; cvta.to.shared.u64 t, %1; cvt.u32.u64 %0, t; }" : "=r"(a) : "l"(p));
    return a;
}
__device__ __forceinline__ float ex2f(float x) {
    float y; asm("ex2.approx.f32 %0, %1;" : "=f"(y) : "f"(x)); return y;
}
__device__ __forceinline__ void ldmx4(uint32_t* r, uint32_t addr) {
    asm volatile("ldmatrix.sync.aligned.m8n8.x4.shared.b16 {%0,%1,%2,%3}, [%4];"
                 : "=r"(r[0]), "=r"(r[1]), "=r"(r[2]), "=r"(r[3]) : "r"(addr));
}
__device__ __forceinline__ void mma16816(float* d, const uint32_t* a, uint32_t b0, uint32_t b1) {
    asm volatile("mma.sync.aligned.m16n8k16.row.col.f32.f16.f16.f32 "
                 "{%0,%1,%2,%3}, {%4,%5,%6,%7}, {%8,%9}, {%0,%1,%2,%3};"
                 : "+f"(d[0]), "+f"(d[1]), "+f"(d[2]), "+f"(d[3])
                 : "r"(a[0]), "r"(a[1]), "r"(a[2]), "r"(a[3]), "r"(b0), "r"(b1));
}

// ---------------- kernel 1: normalize+scale+fp16+transpose -------------------
// 4 threads per pixel, 16 channels each: no register spill, 4x grid for occupancy.
// scale folds sqrt(10 * log2(e)) so 2^(dot) == exp(dot_orig / TEMP).
__global__ void prep_kernel(const float* __restrict__ rgb, const float* __restrict__ ir) {
    int z = blockIdx.z;
    const float* src = z ? ir : rgb;
    __half* dst = z ? g_bh : g_ah;
    int n = blockIdx.y;
    int t = threadIdx.x;
    int l = blockIdx.x * 64 + (t >> 2);   // 64 pixels per block
    int h = t & 3;                        // channel quarter: c in [h*16, h*16+16)
    const float* p = src + n * CC * LL + h * 16 * LL + l;

    float x[16]; float ss = 0.f;
    #pragma unroll
    for (int c = 0; c < 16; ++c) { float v = p[c * LL]; x[c] = v; ss += v * v; }
    ss += __shfl_xor_sync(0xffffffffu, ss, 1);
    ss += __shfl_xor_sync(0xffffffffu, ss, 2);
    float sc = 3.79828262f / fmaxf(sqrtf(ss), 1e-12f);   // sqrt(10*log2(e))

    unsigned u[8];
    #pragma unroll
    for (int k = 0; k < 8; ++k) {
        __half2 h2 = __floats2half2_rn(x[2*k] * sc, x[2*k+1] * sc);
        u[k] = *reinterpret_cast<unsigned*>(&h2);
    }
    uint4* pd = (uint4*)dst + (size_t)(n * LL + l) * 8 + h * 2;
    pd[0] = make_uint4(u[0], u[1], u[2], u[3]);
    pd[1] = make_uint4(u[4], u[5], u[6], u[7]);
}

// ---------------- kernel 2: HMMA (mma.sync fp16) + fused stats ---------------
// grid (8 i-panels, 32 n, 4 j-quarters); each CTA: 128 rows x 256 cols (2 jb)
#define OA    0         // 16384
#define OB    16384     // 16384
#define OCK   32768     // u64[8][128] = 8192
#define OCS   40960     // f32[8][128] = 4096
#define ORK   45056     // u64[2][128] = 2048
#define ORS   47104     // f32[2][128] = 1024
#define SMEM_BYTES 48128

__global__ __launch_bounds__(256, 2) void mma_stats_kernel() {
    extern __shared__ __align__(16) char sm[];
    uint32_t sb = smem_u32(sm);

    int tid  = threadIdx.x;
    int lane = tid & 31;
    int wid  = tid >> 5;
    int wm = wid & 3, wn = wid >> 2;          // 4 m-slices x 2 n-slices
    int m0 = wm * 32;
    int n  = blockIdx.y;
    int i0 = blockIdx.x * 128;
    int qz = blockIdx.z;                      // j-quarter: jb = qz*2 + {0,1}

    unsigned long long* colkey = (unsigned long long*)(sm + OCK);
    float*              colsum = (float*)(sm + OCS);
    unsigned long long* rowkey = (unsigned long long*)(sm + ORK);
    float*              rowsum = (float*)(sm + ORS);

    // load A tile: 128 rows x 128B, SW128-swizzled
    {
        const uint4* s0 = (const uint4*)g_ah + (size_t)(n * LL + i0) * 8;
        int sub = tid & 7, rb = tid >> 3;
        #pragma unroll
        for (int p = 0; p < 4; ++p) {
            int row = p * 32 + rb;
            uint32_t off = SW128((uint32_t)(row * 128 + sub * 16));
            *(uint4*)(sm + OA + off) = s0[row * 8 + sub];
        }
    }

    int lr = lane >> 2, lc2 = (lane & 3) * 2;

    float rm[4], rs[4]; int rj[4];
    #pragma unroll
    for (int r = 0; r < 4; ++r) { rm[r] = 0.f; rs[r] = 0.f; rj[r] = 0; }

    for (int jb = 0; jb < 2; ++jb) {
        int j0 = (qz * 2 + jb) * 128;
        __syncthreads();   // colkey/colsum free, B consumers of prev jb done
        {
            const uint4* s0 = (const uint4*)g_bh + (size_t)(n * LL + j0) * 8;
            int sub = tid & 7, rb = tid >> 3;
            #pragma unroll
            for (int p = 0; p < 4; ++p) {
                int row = p * 32 + rb;
                uint32_t off = SW128((uint32_t)(row * 128 + sub * 16));
                *(uint4*)(sm + OB + off) = s0[row * 8 + sub];
            }
        }
        __syncthreads();

        float acc[2][8][4];
        #pragma unroll
        for (int mt = 0; mt < 2; ++mt)
            #pragma unroll
            for (int nt = 0; nt < 8; ++nt)
                #pragma unroll
                for (int k = 0; k < 4; ++k) acc[mt][nt][k] = 0.f;

        #pragma unroll
        for (int kk = 0; kk < 4; ++kk) {
            uint32_t afr[2][4], bfr[4][4];
            #pragma unroll
            for (int mt = 0; mt < 2; ++mt) {
                uint32_t off = SW128((uint32_t)((m0 + mt * 16 + (lane & 15)) * 128
                                                + kk * 32 + (lane >> 4) * 16));
                ldmx4(afr[mt], sb + OA + off);
            }
            #pragma unroll
            for (int np = 0; np < 4; ++np) {
                uint32_t off = SW128((uint32_t)((wn * 64 + np * 16 + (lane & 15)) * 128
                                                + kk * 32 + (lane >> 4) * 16));
                ldmx4(bfr[np], sb + OB + off);
            }
            #pragma unroll
            for (int mt = 0; mt < 2; ++mt)
                #pragma unroll
                for (int np = 0; np < 4; ++np) {
                    mma16816(acc[mt][2*np],   afr[mt], bfr[np][0], bfr[np][2]);
                    mma16816(acc[mt][2*np+1], afr[mt], bfr[np][1], bfr[np][3]);
                }
        }

        // ---- epilogue: 2^x in place + per-thread row stats ----
        #pragma unroll
        for (int mt = 0; mt < 2; ++mt)
            #pragma unroll
            for (int h = 0; h < 2; ++h) {
                int rid = mt * 2 + h;
                #pragma unroll
                for (int nt = 0; nt < 8; ++nt)
                    #pragma unroll
                    for (int e = 0; e < 2; ++e) {
                        float v = ex2f(acc[mt][nt][h * 2 + e]);
                        acc[mt][nt][h * 2 + e] = v;
                        rs[rid] += v;
                        int j = j0 + wn * 64 + nt * 8 + lc2 + e;
                        if (v > rm[rid]) { rm[rid] = v; rj[rid] = j; }
                    }
            }

        // ---- col partials: 4 local rows, then 2 shuffle rounds (8 groups) ----
        #pragma unroll
        for (int nt = 0; nt < 8; ++nt)
            #pragma unroll
            for (int e = 0; e < 2; ++e) {
                float v0 = acc[0][nt][e],     v1 = acc[0][nt][2 + e];
                float v2 = acc[1][nt][e],     v3 = acc[1][nt][2 + e];
                float cs = v0; cs += v1; cs += v2; cs += v3;
                float cm = v0; int ri = 0;                 // rows asc: +0,+8,+16,+24
                if (v1 > cm) { cm = v1; ri = 1; }
                if (v2 > cm) { cm = v2; ri = 2; }
                if (v3 > cm) { cm = v3; ri = 3; }
                int grow = i0 + m0 + (ri >> 1) * 16 + (ri & 1) * 8 + lr;
                unsigned long long key =
                    ((unsigned long long)__float_as_uint(cm) << 32) |
                    (unsigned)(0xFFFFFFFFu - (unsigned)grow);
                #pragma unroll
                for (int off = 16; off >= 8; off >>= 1) {
                    unsigned long long ko = __shfl_down_sync(0xffffffffu, key, off);
                    float so = __shfl_down_sync(0xffffffffu, cs, off);
                    cs += so;
                    if (ko > key) key = ko;
                }
                if (lane < 8) {
                    int g = wm * 2 + (lane >> 2);          // 8 groups
                    int col = wn * 64 + nt * 8 + lc2 + e;
                    colkey[g * 128 + col] = key;
                    colsum[g * 128 + col] = cs;
                }
            }
        __syncthreads();
        if (tid < 128) {   // merge 8 group partials in fixed order
            unsigned long long key = colkey[tid];
            float sum = colsum[tid];
            #pragma unroll
            for (int g = 1; g < 8; ++g) {
                unsigned long long ko = colkey[g * 128 + tid];
                if (ko > key) key = ko;
                sum += colsum[g * 128 + tid];
            }
            g_ckey[blockIdx.x][n * LL + j0 + tid] = key;
            g_csum[blockIdx.x][n * LL + j0 + tid] = sum;
        }
    }

    // ---- row partials for this quarter: 4-lane tree, wn merge, write --------
    #pragma unroll
    for (int off = 2; off >= 1; off >>= 1) {
        #pragma unroll
        for (int r = 0; r < 4; ++r) {
            float mo = __shfl_down_sync(0xffffffffu, rm[r], off);
            int   jo = __shfl_down_sync(0xffffffffu, rj[r], off);
            float so = __shfl_down_sync(0xffffffffu, rs[r], off);
            rs[r] += so;
            if (mo > rm[r] || (mo == rm[r] && jo < rj[r])) { rm[r] = mo; rj[r] = jo; }
        }
    }
    __syncthreads();   // colkey merge done; rowkey region free
    if ((lane & 3) == 0) {
        #pragma unroll
        for (int r = 0; r < 4; ++r) {
            int row = m0 + (r >> 1) * 16 + (r & 1) * 8 + lr;
            rowkey[wn * 128 + row] =
                ((unsigned long long)__float_as_uint(rm[r]) << 32) |
                (unsigned)(0xFFFFFFFFu - (unsigned)rj[r]);
            rowsum[wn * 128 + row] = rs[r];
        }
    }
    __syncthreads();
    if (tid < 128) {
        unsigned long long k0 = rowkey[tid], k1 = rowkey[128 + tid];
        float s = rowsum[tid] + rowsum[128 + tid];
        unsigned long long k = (k1 > k0) ? k1 : k0;
        int gi = n * LL + i0 + tid;
        g_rkey[qz][gi] = k;
        g_rsum[qz][gi] = s;
    }
}

// ---------------- kernel 3: merge partials + -log terms + final reduce -------
// reference: max_h/(sum_h + eps) * max_o[arg_h] / (sum_o + eps); sum_o at OWN index.
__device__ __forceinline__ unsigned long long row_key(int i) {
    unsigned long long key = g_rkey[0][i];
    #pragma unroll
    for (int q = 1; q < 4; ++q) { unsigned long long k = g_rkey[q][i]; if (k > key) key = k; }
    return key;
}
__device__ __forceinline__ float row_sum(int i) {
    float s = g_rsum[0][i];
    #pragma unroll
    for (int q = 1; q < 4; ++q) s += g_rsum[q][i];
    return s;
}
__device__ __forceinline__ unsigned long long col_key(int i) {
    unsigned long long key = g_ckey[0][i];
    #pragma unroll
    for (int b = 1; b < 8; ++b) { unsigned long long k = g_ckey[b][i]; if (k > key) key = k; }
    return key;
}
__device__ __forceinline__ float col_sum(int i) {
    float s = g_csum[0][i];
    #pragma unroll
    for (int b = 1; b < 8; ++b) s += g_csum[b][i];
    return s;
}

__global__ void loss_kernel(float* __restrict__ out) {   // grid 256 x 256
    int ee = blockIdx.x * 256 + threadIdx.x;   // 0..65535
    int half = ee >> 15;                       // 0: rgb2ir2rgb, 1: ir2rgb2ir
    int idx  = ee & 32767;                     // n*L + l
    int base = idx & ~(LL - 1);
    float mp, sp, mo, so;

    if (half == 0) {
        unsigned long long rk = row_key(idx);
        mp = __uint_as_float((unsigned)(rk >> 32));
        sp = row_sum(idx);
        int a = (int)(0xFFFFFFFFu - (unsigned)(rk & 0xFFFFFFFFu)) & (LL - 1);
        mo = __uint_as_float((unsigned)(col_key(base + a) >> 32));
        so = col_sum(idx);
    } else {
        unsigned long long ck = col_key(idx);
        mp = __uint_as_float((unsigned)(ck >> 32));
        sp = col_sum(idx);
        int a = (int)(0xFFFFFFFFu - (unsigned)(ck & 0xFFFFFFFFu)) & (LL - 1);
        mo = __uint_as_float((unsigned)(row_key(base + a) >> 32));
        so = row_sum(idx);
    }
    float acc = __logf(mp / (sp + EPS) * (mo / (so + EPS)));

    __shared__ float red[256];
    __shared__ unsigned is_last;
    red[threadIdx.x] = acc;
    __syncthreads();
    for (int st = 128; st; st >>= 1) {
        if (threadIdx.x < st) red[threadIdx.x] += red[threadIdx.x + st];
        __syncthreads();
    }
    if (threadIdx.x == 0) {
        g_part[blockIdx.x] = red[0];
        __threadfence();
        is_last = (atomicAdd(&g_cnt, 1u) == 255u) ? 1u : 0u;
    }
    __syncthreads();
    if (is_last) {
        __threadfence();
        red[threadIdx.x] = __ldcg(&g_part[threadIdx.x]);
        __syncthreads();
        for (int st = 128; st; st >>= 1) {
            if (threadIdx.x < st) red[threadIdx.x] += red[threadIdx.x + st];
            __syncthreads();
        }
        if (threadIdx.x == 0) {
            out[0] = -red[0] * (1.0f / 65536.0f);
            g_cnt = 0;                      // reset for graph replay
        }
    }
}

// ---------------- launch ------------------------------------------------------
extern "C" void kernel_launch(void* const* d_in, const int* in_sizes, int n_in,
                              void* d_out, int out_size) {
    const float* rgb = (const float*)d_in[0];
    const float* ir  = (const float*)d_in[1];

    cudaFuncSetAttribute(mma_stats_kernel,
                         cudaFuncAttributeMaxDynamicSharedMemorySize, SMEM_BYTES);

    prep_kernel<<<dim3(16, 32, 2), 256>>>(rgb, ir);
    mma_stats_kernel<<<dim3(8, 32, 4), 256, SMEM_BYTES>>>();
    loss_kernel<<<256, 256>>>((float*)d_out);
}